// round 9
// baseline (speedup 1.0000x reference)
#include <cuda_runtime.h>
#include <math.h>
#include <stdint.h>

// Problem constants
#define ETOT 1024
#define NTOK 8192
#define SEQ  2048
#define NH   16
#define HD   64
#define MLPD 4096

// GEMM tile config
#define BM 128
#define BN 128
#define BK 32
#define SPAD 36
#define STAGE_FLOATS (2 * 128 * SPAD)                  // As+Bs per stage
#define NSTAGE 3
#define SMEM_GEMM (NSTAGE * STAGE_FLOATS * 4)          // 110592 B

// Attention config
#define AQ 128
#define AKV 64
#define APAD 76
#define SMEM_ATTN ((2 * AKV + AQ) * APAD * 4)          // 77824 B

// Scratch
__device__ float g_h[NTOK * ETOT];
__device__ float g_qkv[NTOK * 3 * ETOT];
__device__ float g_attn[NTOK * ETOT];
__device__ float g_x2[NTOK * ETOT];
__device__ float g_mid[NTOK * MLPD];
__device__ float g_wq[3 * ETOT * ETOT];   // rounded weights
__device__ float g_wf[ETOT * ETOT];
__device__ float g_w1[MLPD * ETOT];
__device__ float g_w2[ETOT * MLPD];

// ---------------------------------------------------------------------------
// Helpers
// ---------------------------------------------------------------------------
__device__ __forceinline__ uint32_t f2tf32(float x) {
    uint32_t r;
    asm("cvt.rna.tf32.f32 %0, %1;" : "=r"(r) : "f"(x));
    return r;
}

__device__ __forceinline__ float f2tf32f(float x) {
    return __uint_as_float(f2tf32(x));
}

__device__ __forceinline__ void mma_tf32(float* d, const uint32_t* a,
                                         const uint32_t* b) {
    asm volatile(
        "mma.sync.aligned.m16n8k8.row.col.f32.tf32.tf32.f32 "
        "{%0,%1,%2,%3}, {%4,%5,%6,%7}, {%8,%9}, {%0,%1,%2,%3};"
        : "+f"(d[0]), "+f"(d[1]), "+f"(d[2]), "+f"(d[3])
        : "r"(a[0]), "r"(a[1]), "r"(a[2]), "r"(a[3]), "r"(b[0]), "r"(b[1]));
}

__device__ __forceinline__ void cp16(uint32_t dst_smem, const float* src) {
    asm volatile("cp.async.cg.shared.global [%0], [%1], 16;"
                 :: "r"(dst_smem), "l"(src));
}

__device__ __forceinline__ uint32_t smem_u32(const void* p) {
    uint32_t a;
    asm("{ .reg .u64 t; cvta.to.shared.u64 t, %1; cvt.u32.u64 %0, t; }"
        : "=r"(a) : "l"(p));
    return a;
}

// ---------------------------------------------------------------------------
// Fused weight rounding: one launch over all 4 weight tensors (float4 elems)
// segments (in float4): wq 786432 | wf 262144 | w1 1048576 | w2 1048576
// ---------------------------------------------------------------------------
__global__ __launch_bounds__(256) void round_all(
    const float* __restrict__ qkv_w, const float* __restrict__ fc_w,
    const float* __restrict__ w1, const float* __restrict__ w2,
    float* __restrict__ owq, float* __restrict__ owf,
    float* __restrict__ ow1, float* __restrict__ ow2)
{
    int i = blockIdx.x * 256 + threadIdx.x;
    const float4* src;
    float4* dst;
    if (i < 786432) {
        src = (const float4*)qkv_w; dst = (float4*)owq;
    } else if (i < 786432 + 262144) {
        i -= 786432;
        src = (const float4*)fc_w; dst = (float4*)owf;
    } else if (i < 786432 + 262144 + 1048576) {
        i -= 786432 + 262144;
        src = (const float4*)w1; dst = (float4*)ow1;
    } else {
        i -= 786432 + 262144 + 1048576;
        src = (const float4*)w2; dst = (float4*)ow2;
    }
    float4 v = src[i];
    v.x = f2tf32f(v.x); v.y = f2tf32f(v.y);
    v.z = f2tf32f(v.z); v.w = f2tf32f(v.w);
    dst[i] = v;
}
#define ROUND_BLOCKS ((786432 + 262144 + 1048576 + 1048576) / 256)

// ---------------------------------------------------------------------------
// LayerNorm (float4, rounds output to tf32 — output only feeds mma)
// ---------------------------------------------------------------------------
__global__ __launch_bounds__(256) void ln_kernel(
    const float* __restrict__ x, const float* __restrict__ g,
    const float* __restrict__ b, float* __restrict__ out)
{
    const int row = blockIdx.x;
    const int tid = threadIdx.x;
    const float4 v = ((const float4*)(x + (long)row * ETOT))[tid];
    float s = v.x + v.y + v.z + v.w;
    float s2 = v.x * v.x + v.y * v.y + v.z * v.z + v.w * v.w;
#pragma unroll
    for (int o = 16; o; o >>= 1) {
        s  += __shfl_down_sync(0xffffffffu, s, o);
        s2 += __shfl_down_sync(0xffffffffu, s2, o);
    }
    __shared__ float sm[8], sm2[8];
    if ((tid & 31) == 0) { sm[tid >> 5] = s; sm2[tid >> 5] = s2; }
    __syncthreads();
    float ts = 0.f, ts2 = 0.f;
#pragma unroll
    for (int i = 0; i < 8; i++) { ts += sm[i]; ts2 += sm2[i]; }
    const float mu = ts * (1.0f / ETOT);
    const float var = ts2 * (1.0f / ETOT) - mu * mu;
    const float r = rsqrtf(var + 1e-5f);
    const float4 gv = ((const float4*)g)[tid];
    const float4 bv = ((const float4*)b)[tid];
    float4 o4;
    o4.x = f2tf32f((v.x - mu) * r * gv.x + bv.x);
    o4.y = f2tf32f((v.y - mu) * r * gv.y + bv.y);
    o4.z = f2tf32f((v.z - mu) * r * gv.z + bv.z);
    o4.w = f2tf32f((v.w - mu) * r * gv.w + bv.w);
    ((float4*)(out + (long)row * ETOT))[tid] = o4;
}

// ---------------------------------------------------------------------------
// tf32 GEMM, 3-stage cp.async pipeline, one __syncthreads per tile.
// Inputs must be pre-rounded to tf32.
// ---------------------------------------------------------------------------
template <bool BIAS, bool RES, bool GELU, bool ROUND>
__global__ __launch_bounds__(256, 2) void tc_gemm(
    const float* __restrict__ A, const float* __restrict__ W,
    const float* __restrict__ bias, const float* __restrict__ res,
    float* __restrict__ C, int M, int N, int K)
{
    extern __shared__ float smem[];

    const int tid = threadIdx.x;
    const int m0 = blockIdx.y * BM;
    const int n0 = blockIdx.x * BN;

    const int lrow = tid >> 3;
    const int lcol = (tid & 7) * 4;

    const float* Ap = A + (size_t)(m0 + lrow) * K + lcol;
    const float* Wp = W + (size_t)(n0 + lrow) * K + lcol;

    const uint32_t sb = smem_u32(smem);

    const int wid = tid >> 5;
    const int lane = tid & 31;
    const int wm = (wid >> 2) * 64;
    const int wn = (wid & 3) * 32;
    const int g = lane >> 2;
    const int cg = lane & 3;

    float acc[4][4][4];
#pragma unroll
    for (int mi = 0; mi < 4; mi++)
#pragma unroll
        for (int nj = 0; nj < 4; nj++)
#pragma unroll
            for (int e = 0; e < 4; e++) acc[mi][nj][e] = 0.f;

    auto issue = [&](int st, int kt) {
        const uint32_t dA = sb + (uint32_t)(st * STAGE_FLOATS) * 4;
        const uint32_t dB = dA + 128 * SPAD * 4;
#pragma unroll
        for (int it = 0; it < 4; it++) {
            const uint32_t off = (uint32_t)((lrow + it * 32) * SPAD + lcol) * 4;
            cp16(dA + off, Ap + (size_t)(it * 32) * K + kt);
            cp16(dB + off, Wp + (size_t)(it * 32) * K + kt);
        }
        asm volatile("cp.async.commit_group;");
    };

    // Prologue: stages 0,1
    issue(0, 0);
    issue(1, BK);

    const int T = K / BK;
    for (int t = 0; t < T; t++) {
        // stage t ready when at most 1 group (t+1) pending
        asm volatile("cp.async.wait_group 1;");
        __syncthreads();   // also orders compute(t-1) before overwrite below

        if (t + 2 < T) issue((t + 2) % NSTAGE, (t + 2) * BK);
        else           asm volatile("cp.async.commit_group;");  // keep group count in step

        const float* As = smem + (t % NSTAGE) * STAGE_FLOATS;
        const float* Bs = As + 128 * SPAD;

#pragma unroll
        for (int ks = 0; ks < 4; ks++) {
            const int k = ks * 8;
            uint32_t af[4][4];
#pragma unroll
            for (int mi = 0; mi < 4; mi++) {
                const int mb = wm + mi * 16;
                af[mi][0] = __float_as_uint(As[(mb + g)     * SPAD + k + cg]);
                af[mi][1] = __float_as_uint(As[(mb + g + 8) * SPAD + k + cg]);
                af[mi][2] = __float_as_uint(As[(mb + g)     * SPAD + k + cg + 4]);
                af[mi][3] = __float_as_uint(As[(mb + g + 8) * SPAD + k + cg + 4]);
            }
            uint32_t bf[4][2];
#pragma unroll
            for (int nj = 0; nj < 4; nj++) {
                const int nb = wn + nj * 8 + g;
                bf[nj][0] = __float_as_uint(Bs[nb * SPAD + k + cg]);
                bf[nj][1] = __float_as_uint(Bs[nb * SPAD + k + cg + 4]);
            }
#pragma unroll
            for (int mi = 0; mi < 4; mi++)
#pragma unroll
                for (int nj = 0; nj < 4; nj++)
                    mma_tf32(acc[mi][nj], af[mi], bf[nj]);
        }
    }

    // Epilogue
#pragma unroll
    for (int mi = 0; mi < 4; mi++) {
        const int mA = m0 + wm + mi * 16 + g;
        const int mB = mA + 8;
#pragma unroll
        for (int nj = 0; nj < 4; nj++) {
            const int n = n0 + wn + nj * 8 + 2 * cg;
            float2 v0 = make_float2(acc[mi][nj][0], acc[mi][nj][1]);
            float2 v1 = make_float2(acc[mi][nj][2], acc[mi][nj][3]);
            if (BIAS) {
                const float b0 = bias[n], b1 = bias[n + 1];
                v0.x += b0; v0.y += b1;
                v1.x += b0; v1.y += b1;
            }
            if (GELU) {
                v0.x = 0.5f * v0.x * (1.0f + erff(v0.x * 0.70710678118654752f));
                v0.y = 0.5f * v0.y * (1.0f + erff(v0.y * 0.70710678118654752f));
                v1.x = 0.5f * v1.x * (1.0f + erff(v1.x * 0.70710678118654752f));
                v1.y = 0.5f * v1.y * (1.0f + erff(v1.y * 0.70710678118654752f));
            }
            if (RES) {
                const float2 r0 = *(const float2*)(res + (size_t)mA * N + n);
                const float2 r1 = *(const float2*)(res + (size_t)mB * N + n);
                v0.x += r0.x; v0.y += r0.y;
                v1.x += r1.x; v1.y += r1.y;
            }
            if (ROUND) {
                v0.x = f2tf32f(v0.x); v0.y = f2tf32f(v0.y);
                v1.x = f2tf32f(v1.x); v1.y = f2tf32f(v1.y);
            }
            *(float2*)(C + (size_t)mA * N + n) = v0;
            *(float2*)(C + (size_t)mB * N + n) = v1;
        }
    }
}

// ---------------------------------------------------------------------------
// tf32 mma flash attention (unchanged from R8).
// ---------------------------------------------------------------------------
__global__ __launch_bounds__(256, 2) void attn_mma(
    const float* __restrict__ qkv, float* __restrict__ out)
{
    extern __shared__ float asmem[];
    float* Ks = asmem;
    float* Vs = asmem + AKV * APAD;
    float* Ps = asmem + 2 * AKV * APAD;

    const int bh = blockIdx.y;
    const int b = bh >> 4;
    const int h = bh & 15;
    const int q0 = blockIdx.x * AQ;
    const int tid = threadIdx.x;
    const int wid = tid >> 5;
    const int lane = tid & 31;
    const int g = lane >> 2;
    const int cg = lane & 3;
    const int wrow = wid * 16;

    const size_t base = (size_t)b * SEQ * 3 * ETOT;

    for (int idx = tid; idx < AQ * HD / 2; idx += 256) {
        const int r = idx >> 5;
        const int c = (idx & 31) * 2;
        const float2 qv = *(const float2*)(qkv + base + (size_t)(q0 + r) * (3 * ETOT) + h * HD + c);
        Ps[r * APAD + c] = qv.x;
        Ps[r * APAD + c + 1] = qv.y;
    }
    __syncthreads();

    uint32_t qf[8][4];
#pragma unroll
    for (int ks = 0; ks < 8; ks++) {
        const int k = ks * 8;
        qf[ks][0] = __float_as_uint(Ps[(wrow + g)     * APAD + k + cg]);
        qf[ks][1] = __float_as_uint(Ps[(wrow + g + 8) * APAD + k + cg]);
        qf[ks][2] = __float_as_uint(Ps[(wrow + g)     * APAD + k + cg + 4]);
        qf[ks][3] = __float_as_uint(Ps[(wrow + g + 8) * APAD + k + cg + 4]);
    }
    __syncthreads();

    float o[8][4];
#pragma unroll
    for (int nj = 0; nj < 8; nj++)
#pragma unroll
        for (int e = 0; e < 4; e++) o[nj][e] = 0.f;
    float m0 = -1e30f, m1 = -1e30f, l0 = 0.f, l1 = 0.f;

    for (int k0 = 0; k0 < SEQ; k0 += AKV) {
        for (int idx = tid; idx < AKV * HD / 2; idx += 256) {
            const int r = idx >> 5;
            const int c = (idx & 31) * 2;
            const size_t ro = base + (size_t)(k0 + r) * (3 * ETOT) + h * HD + c;
            const float2 kv = *(const float2*)(qkv + ro + ETOT);
            const float2 vv = *(const float2*)(qkv + ro + 2 * ETOT);
            Ks[r * APAD + c] = kv.x; Ks[r * APAD + c + 1] = kv.y;
            Vs[r * APAD + c] = vv.x; Vs[r * APAD + c + 1] = vv.y;
        }
        __syncthreads();

        float s[8][4];
#pragma unroll
        for (int nj = 0; nj < 8; nj++)
#pragma unroll
            for (int e = 0; e < 4; e++) s[nj][e] = 0.f;
#pragma unroll
        for (int ks = 0; ks < 8; ks++) {
            const int k = ks * 8;
            uint32_t bf[8][2];
#pragma unroll
            for (int nj = 0; nj < 8; nj++) {
                const int kr = nj * 8 + g;
                bf[nj][0] = __float_as_uint(Ks[kr * APAD + k + cg]);
                bf[nj][1] = __float_as_uint(Ks[kr * APAD + k + cg + 4]);
            }
#pragma unroll
            for (int nj = 0; nj < 8; nj++)
                mma_tf32(s[nj], qf[ks], bf[nj]);
        }

        float mn0 = -1e30f, mn1 = -1e30f;
#pragma unroll
        for (int nj = 0; nj < 8; nj++) {
#pragma unroll
            for (int e = 0; e < 4; e++) s[nj][e] *= 0.125f;
            mn0 = fmaxf(mn0, fmaxf(s[nj][0], s[nj][1]));
            mn1 = fmaxf(mn1, fmaxf(s[nj][2], s[nj][3]));
        }
        mn0 = fmaxf(mn0, __shfl_xor_sync(0xffffffffu, mn0, 1));
        mn0 = fmaxf(mn0, __shfl_xor_sync(0xffffffffu, mn0, 2));
        mn1 = fmaxf(mn1, __shfl_xor_sync(0xffffffffu, mn1, 1));
        mn1 = fmaxf(mn1, __shfl_xor_sync(0xffffffffu, mn1, 2));
        const float mN0 = fmaxf(m0, mn0);
        const float mN1 = fmaxf(m1, mn1);
        const float c0 = __expf(m0 - mN0);
        const float c1 = __expf(m1 - mN1);
        m0 = mN0; m1 = mN1;
        float sum0 = 0.f, sum1 = 0.f;
#pragma unroll
        for (int nj = 0; nj < 8; nj++) {
            s[nj][0] = __expf(s[nj][0] - mN0);
            s[nj][1] = __expf(s[nj][1] - mN0);
            s[nj][2] = __expf(s[nj][2] - mN1);
            s[nj][3] = __expf(s[nj][3] - mN1);
            sum0 += s[nj][0] + s[nj][1];
            sum1 += s[nj][2] + s[nj][3];
        }
        sum0 += __shfl_xor_sync(0xffffffffu, sum0, 1);
        sum0 += __shfl_xor_sync(0xffffffffu, sum0, 2);
        sum1 += __shfl_xor_sync(0xffffffffu, sum1, 1);
        sum1 += __shfl_xor_sync(0xffffffffu, sum1, 2);
        l0 = l0 * c0 + sum0;
        l1 = l1 * c1 + sum1;
#pragma unroll
        for (int nj = 0; nj < 8; nj++) {
            o[nj][0] *= c0; o[nj][1] *= c0;
            o[nj][2] *= c1; o[nj][3] *= c1;
        }

#pragma unroll
        for (int nj = 0; nj < 8; nj++) {
            const int n = nj * 8 + 2 * cg;
            Ps[(wrow + g)     * APAD + n]     = f2tf32f(s[nj][0]);
            Ps[(wrow + g)     * APAD + n + 1] = f2tf32f(s[nj][1]);
            Ps[(wrow + g + 8) * APAD + n]     = f2tf32f(s[nj][2]);
            Ps[(wrow + g + 8) * APAD + n + 1] = f2tf32f(s[nj][3]);
        }
        __syncwarp();

#pragma unroll
        for (int ks = 0; ks < 8; ks++) {
            const int k = ks * 8;
            uint32_t pf[4];
            pf[0] = __float_as_uint(Ps[(wrow + g)     * APAD + k + cg]);
            pf[1] = __float_as_uint(Ps[(wrow + g + 8) * APAD + k + cg]);
            pf[2] = __float_as_uint(Ps[(wrow + g)     * APAD + k + cg + 4]);
            pf[3] = __float_as_uint(Ps[(wrow + g + 8) * APAD + k + cg + 4]);
#pragma unroll
            for (int nj = 0; nj < 8; nj++) {
                uint32_t bf[2];
                bf[0] = __float_as_uint(Vs[(k + cg)     * APAD + nj * 8 + g]);
                bf[1] = __float_as_uint(Vs[(k + cg + 4) * APAD + nj * 8 + g]);
                mma_tf32(o[nj], pf, bf);
            }
        }
        __syncthreads();
    }

    const float inv0 = 1.0f / l0;
    const float inv1 = 1.0f / l1;
    const int tokA = q0 + wrow + g;
    const int tokB = tokA + 8;
    const size_t rA = (size_t)(b * SEQ + tokA) * ETOT + h * HD;
    const size_t rB = (size_t)(b * SEQ + tokB) * ETOT + h * HD;
#pragma unroll
    for (int nj = 0; nj < 8; nj++) {
        const int n = nj * 8 + 2 * cg;
        float2 v0 = make_float2(f2tf32f(o[nj][0] * inv0), f2tf32f(o[nj][1] * inv0));
        float2 v1 = make_float2(f2tf32f(o[nj][2] * inv1), f2tf32f(o[nj][3] * inv1));
        *(float2*)(out + rA + n) = v0;
        *(float2*)(out + rB + n) = v1;
    }
}

// ---------------------------------------------------------------------------
// Host launcher
// ---------------------------------------------------------------------------
extern "C" void kernel_launch(void* const* d_in, const int* in_sizes, int n_in,
                              void* d_out, int out_size)
{
    const float* x     = (const float*)d_in[0];
    const float* qkv_w = (const float*)d_in[1];
    const float* fc_w  = (const float*)d_in[2];
    const float* fc_b  = (const float*)d_in[3];
    const float* ln1_g = (const float*)d_in[4];
    const float* ln1_b = (const float*)d_in[5];
    const float* ln2_g = (const float*)d_in[6];
    const float* ln2_b = (const float*)d_in[7];
    const float* w1    = (const float*)d_in[8];
    const float* b1    = (const float*)d_in[9];
    const float* w2    = (const float*)d_in[10];
    const float* b2    = (const float*)d_in[11];
    float* out = (float*)d_out;

    void *ph, *pq, *pa, *px2, *pm, *pwq, *pwf, *pw1, *pw2;
    cudaGetSymbolAddress(&ph,  g_h);
    cudaGetSymbolAddress(&pq,  g_qkv);
    cudaGetSymbolAddress(&pa,  g_attn);
    cudaGetSymbolAddress(&px2, g_x2);
    cudaGetSymbolAddress(&pm,  g_mid);
    cudaGetSymbolAddress(&pwq, g_wq);
    cudaGetSymbolAddress(&pwf, g_wf);
    cudaGetSymbolAddress(&pw1, g_w1);
    cudaGetSymbolAddress(&pw2, g_w2);
    float* h    = (float*)ph;
    float* qkvb = (float*)pq;
    float* attn = (float*)pa;
    float* x2   = (float*)px2;
    float* mid  = (float*)pm;
    float* wq   = (float*)pwq;
    float* wf   = (float*)pwf;
    float* w1r  = (float*)pw1;
    float* w2r  = (float*)pw2;

    cudaFuncSetAttribute(tc_gemm<false, false, false, true>,
                         cudaFuncAttributeMaxDynamicSharedMemorySize, SMEM_GEMM);
    cudaFuncSetAttribute(tc_gemm<true, true, false, false>,
                         cudaFuncAttributeMaxDynamicSharedMemorySize, SMEM_GEMM);
    cudaFuncSetAttribute(tc_gemm<true, false, true, true>,
                         cudaFuncAttributeMaxDynamicSharedMemorySize, SMEM_GEMM);
    cudaFuncSetAttribute(attn_mma,
                         cudaFuncAttributeMaxDynamicSharedMemorySize, SMEM_ATTN);

    // 0. Round all weights to tf32 (single launch)
    round_all<<<ROUND_BLOCKS, 256>>>(qkv_w, fc_w, w1, w2, wq, wf, w1r, w2r);

    // 1. h = LN1(x)  (tf32-rounded)
    ln_kernel<<<NTOK, 256>>>(x, ln1_g, ln1_b, h);

    // 2. qkv = h @ qkv_w^T  (tf32-rounded output)
    tc_gemm<false, false, false, true>
        <<<dim3((3 * ETOT) / BN, NTOK / BM), 256, SMEM_GEMM>>>(
        h, wq, nullptr, nullptr, qkvb, NTOK, 3 * ETOT, ETOT);

    // 3. attention (tf32 mma, tf32-rounded output)
    attn_mma<<<dim3(SEQ / AQ, 4 * NH), 256, SMEM_ATTN>>>(qkvb, attn);

    // 4. x2 = x + attn @ fc_w^T + fc_b  (fp32 out)
    tc_gemm<true, true, false, false>
        <<<dim3(ETOT / BN, NTOK / BM), 256, SMEM_GEMM>>>(
        attn, wf, fc_b, x, x2, NTOK, ETOT, ETOT);

    // 5. h = LN2(x2)  (tf32-rounded)
    ln_kernel<<<NTOK, 256>>>(x2, ln2_g, ln2_b, h);

    // 6. mid = gelu(h @ w1^T + b1)  (tf32-rounded output)
    tc_gemm<true, false, true, true>
        <<<dim3(MLPD / BN, NTOK / BM), 256, SMEM_GEMM>>>(
        h, w1r, b1, nullptr, mid, NTOK, MLPD, ETOT);

    // 7. out = x2 + mid @ w2^T + b2  (fp32 out)
    tc_gemm<true, true, false, false>
        <<<dim3(ETOT / BN, NTOK / BM), 256, SMEM_GEMM>>>(
        mid, w2r, b2, x2, out, NTOK, ETOT, MLPD);
}

// round 12
// speedup vs baseline: 1.5456x; 1.5456x over previous
#include <cuda_runtime.h>
#include <cuda_bf16.h>
#include <math.h>
#include <stdint.h>

// Problem constants
#define ETOT 1024
#define NTOK 8192
#define SEQ  2048
#define NH   16
#define HD   64
#define MLPD 4096

// GEMM tile config (bf16 mma m16n8k16)
#define BM 128
#define BN 128
#define BK 64
#define GROWB 144                              // smem row stride bytes (64 bf16 + 16B pad)
#define G_STAGE (2 * 128 * GROWB)              // A+B per stage = 36864 B
#define SMEM_GEMM (2 * G_STAGE)                // 73728 B

// Attention config
#define AQ 128
#define AKV 64
#define KV_STAGE (2 * 64 * GROWB)              // K+V per stage = 18432 B
#define SMEM_ATTN (128 * GROWB + 2 * KV_STAGE) // Q + 2 KV stages = 55296 B

// Scratch (allocation-free rule: __device__ globals)
__device__ __nv_bfloat16 g_h[NTOK * ETOT];
__device__ __nv_bfloat16 g_qkv[NTOK * 3 * ETOT];
__device__ __nv_bfloat16 g_attn[NTOK * ETOT];
__device__ float         g_x2[NTOK * ETOT];
__device__ __nv_bfloat16 g_mid[NTOK * MLPD];
__device__ __nv_bfloat16 g_wq[3 * ETOT * ETOT];
__device__ __nv_bfloat16 g_wf[ETOT * ETOT];
__device__ __nv_bfloat16 g_w1[MLPD * ETOT];
__device__ __nv_bfloat16 g_w2[ETOT * MLPD];

// ---------------------------------------------------------------------------
// Helpers
// ---------------------------------------------------------------------------
__device__ __forceinline__ uint32_t packbf(float lo, float hi) {
    __nv_bfloat162 t;
    t.x = __float2bfloat16_rn(lo);
    t.y = __float2bfloat16_rn(hi);
    return *reinterpret_cast<uint32_t*>(&t);
}

__device__ __forceinline__ void mma_bf16(float* d, const uint32_t* a,
                                         const uint32_t* b) {
    asm volatile(
        "mma.sync.aligned.m16n8k16.row.col.f32.bf16.bf16.f32 "
        "{%0,%1,%2,%3}, {%4,%5,%6,%7}, {%8,%9}, {%0,%1,%2,%3};"
        : "+f"(d[0]), "+f"(d[1]), "+f"(d[2]), "+f"(d[3])
        : "r"(a[0]), "r"(a[1]), "r"(a[2]), "r"(a[3]), "r"(b[0]), "r"(b[1]));
}

__device__ __forceinline__ void ldm_x4(uint32_t* r, uint32_t addr) {
    asm volatile("ldmatrix.sync.aligned.m8n8.x4.shared.b16 {%0,%1,%2,%3}, [%4];"
                 : "=r"(r[0]), "=r"(r[1]), "=r"(r[2]), "=r"(r[3]) : "r"(addr));
}

__device__ __forceinline__ void ldm_x4_t(uint32_t* r, uint32_t addr) {
    asm volatile("ldmatrix.sync.aligned.m8n8.x4.trans.shared.b16 {%0,%1,%2,%3}, [%4];"
                 : "=r"(r[0]), "=r"(r[1]), "=r"(r[2]), "=r"(r[3]) : "r"(addr));
}

__device__ __forceinline__ void cp16(uint32_t dst_smem, const void* src) {
    asm volatile("cp.async.cg.shared.global [%0], [%1], 16;"
                 :: "r"(dst_smem), "l"(src));
}

__device__ __forceinline__ uint32_t smem_u32(const void* p) {
    uint32_t a;
    asm("{ .reg .u64 t; cvta.to.shared.u64 t, %1; cvt.u32.u64 %0, t; }"
        : "=r"(a) : "l"(p));
    return a;
}

// ---------------------------------------------------------------------------
// Fused weight conversion fp32 -> bf16 (single launch, 4 segments of float4)
// ---------------------------------------------------------------------------
__global__ __launch_bounds__(256) void round_all(
    const float* __restrict__ qkv_w, const float* __restrict__ fc_w,
    const float* __restrict__ w1, const float* __restrict__ w2,
    __nv_bfloat16* __restrict__ owq, __nv_bfloat16* __restrict__ owf,
    __nv_bfloat16* __restrict__ ow1, __nv_bfloat16* __restrict__ ow2)
{
    int i = blockIdx.x * 256 + threadIdx.x;
    const float4* src;
    __nv_bfloat16* dst;
    if (i < 786432) {
        src = (const float4*)qkv_w; dst = owq;
    } else if (i < 786432 + 262144) {
        i -= 786432;
        src = (const float4*)fc_w; dst = owf;
    } else if (i < 786432 + 262144 + 1048576) {
        i -= 786432 + 262144;
        src = (const float4*)w1; dst = ow1;
    } else {
        i -= 786432 + 262144 + 1048576;
        src = (const float4*)w2; dst = ow2;
    }
    const float4 v = src[i];
    uint2 w;
    w.x = packbf(v.x, v.y);
    w.y = packbf(v.z, v.w);
    ((uint2*)dst)[i] = w;
}
#define ROUND_BLOCKS ((786432 + 262144 + 1048576 + 1048576) / 256)

// ---------------------------------------------------------------------------
// LayerNorm: fp32 in, bf16 out (feeds mma only)
// ---------------------------------------------------------------------------
__global__ __launch_bounds__(256) void ln_kernel(
    const float* __restrict__ x, const float* __restrict__ g,
    const float* __restrict__ b, __nv_bfloat16* __restrict__ out)
{
    const int row = blockIdx.x;
    const int tid = threadIdx.x;
    const float4 v = ((const float4*)(x + (long)row * ETOT))[tid];
    float s = v.x + v.y + v.z + v.w;
    float s2 = v.x * v.x + v.y * v.y + v.z * v.z + v.w * v.w;
#pragma unroll
    for (int o = 16; o; o >>= 1) {
        s  += __shfl_down_sync(0xffffffffu, s, o);
        s2 += __shfl_down_sync(0xffffffffu, s2, o);
    }
    __shared__ float sm[8], sm2[8];
    if ((tid & 31) == 0) { sm[tid >> 5] = s; sm2[tid >> 5] = s2; }
    __syncthreads();
    float ts = 0.f, ts2 = 0.f;
#pragma unroll
    for (int i = 0; i < 8; i++) { ts += sm[i]; ts2 += sm2[i]; }
    const float mu = ts * (1.0f / ETOT);
    const float var = ts2 * (1.0f / ETOT) - mu * mu;
    const float r = rsqrtf(var + 1e-5f);
    const float4 gv = ((const float4*)g)[tid];
    const float4 bv = ((const float4*)b)[tid];
    uint2 w;
    w.x = packbf((v.x - mu) * r * gv.x + bv.x, (v.y - mu) * r * gv.y + bv.y);
    w.y = packbf((v.z - mu) * r * gv.z + bv.z, (v.w - mu) * r * gv.w + bv.w);
    ((uint2*)(out + (long)row * ETOT))[tid] = w;
}

// ---------------------------------------------------------------------------
// bf16 GEMM: C[M,N] = A[M,K] @ W[N,K]^T (+bias)(+GELU)(+residual)
// BM=BN=128, BK=64, 2-stage cp.async, ldmatrix fragments, fp32 accum.
// ---------------------------------------------------------------------------
template <bool BIAS, bool RES, bool GELU, bool OUTBF>
__global__ __launch_bounds__(256, 2) void bf_gemm(
    const __nv_bfloat16* __restrict__ A, const __nv_bfloat16* __restrict__ W,
    const float* __restrict__ bias, const float* __restrict__ res,
    float* __restrict__ Cf, __nv_bfloat16* __restrict__ Cb,
    int M, int N, int K)
{
    extern __shared__ char smem[];
    const uint32_t sb = smem_u32(smem);

    const int tid = threadIdx.x;
    const int m0 = blockIdx.y * BM;
    const int n0 = blockIdx.x * BN;

    // loader: row = tid>>1 (0..127), 4 chunks of 16B starting at (tid&1)*4
    const int lrow = tid >> 1;
    const int lc4 = (tid & 1) * 4;
    const __nv_bfloat16* Ap = A + (size_t)(m0 + lrow) * K + lc4 * 8;
    const __nv_bfloat16* Wp = W + (size_t)(n0 + lrow) * K + lc4 * 8;
    const uint32_t dro = (uint32_t)(lrow * GROWB + lc4 * 16);

    const int wid = tid >> 5;
    const int lane = tid & 31;
    const int wm = (wid >> 2) * 64;
    const int wn = (wid & 3) * 32;
    const int g = lane >> 2;
    const int cg = lane & 3;
    const uint32_t lmrow = (lane & 15);
    const uint32_t lmsel = ((lane >> 4) & 1) * 16;

    float acc[4][4][4];
#pragma unroll
    for (int mi = 0; mi < 4; mi++)
#pragma unroll
        for (int nj = 0; nj < 4; nj++)
#pragma unroll
            for (int e = 0; e < 4; e++) acc[mi][nj][e] = 0.f;

    auto issue = [&](int st, int kt) {
        const uint32_t dA = sb + st * G_STAGE + dro;
        const uint32_t dB = dA + 128 * GROWB;
#pragma unroll
        for (int i = 0; i < 4; i++) {
            cp16(dA + i * 16, Ap + kt + i * 8);
            cp16(dB + i * 16, Wp + kt + i * 8);
        }
        asm volatile("cp.async.commit_group;");
    };

    issue(0, 0);

    const int T = K / BK;
    for (int t = 0; t < T; t++) {
        if (t + 1 < T) {
            issue((t + 1) & 1, (t + 1) * BK);
            asm volatile("cp.async.wait_group 1;");
        } else {
            asm volatile("cp.async.wait_group 0;");
        }
        __syncthreads();

        const uint32_t sA = sb + (t & 1) * G_STAGE;
        const uint32_t sB = sA + 128 * GROWB;

#pragma unroll
        for (int ks = 0; ks < 4; ks++) {
            uint32_t af[4][4];
#pragma unroll
            for (int mi = 0; mi < 4; mi++)
                ldm_x4(af[mi], sA + (wm + mi * 16 + lmrow) * GROWB + ks * 32 + lmsel);
            uint32_t bm[2][4];
#pragma unroll
            for (int p = 0; p < 2; p++)
                ldm_x4(bm[p], sB + (wn + p * 16 + lmrow) * GROWB + ks * 32 + lmsel);
#pragma unroll
            for (int mi = 0; mi < 4; mi++)
#pragma unroll
                for (int nj = 0; nj < 4; nj++) {
                    uint32_t bf[2] = { bm[nj >> 1][nj & 1], bm[nj >> 1][(nj & 1) + 2] };
                    mma_bf16(acc[mi][nj], af[mi], bf);
                }
        }
        __syncthreads();
    }

    // Epilogue
#pragma unroll
    for (int mi = 0; mi < 4; mi++) {
        const int mA = m0 + wm + mi * 16 + g;
        const int mB = mA + 8;
#pragma unroll
        for (int nj = 0; nj < 4; nj++) {
            const int n = n0 + wn + nj * 8 + 2 * cg;
            float2 v0 = make_float2(acc[mi][nj][0], acc[mi][nj][1]);
            float2 v1 = make_float2(acc[mi][nj][2], acc[mi][nj][3]);
            if (BIAS) {
                const float b0 = bias[n], b1 = bias[n + 1];
                v0.x += b0; v0.y += b1;
                v1.x += b0; v1.y += b1;
            }
            if (GELU) {
                v0.x = 0.5f * v0.x * (1.0f + erff(v0.x * 0.70710678118654752f));
                v0.y = 0.5f * v0.y * (1.0f + erff(v0.y * 0.70710678118654752f));
                v1.x = 0.5f * v1.x * (1.0f + erff(v1.x * 0.70710678118654752f));
                v1.y = 0.5f * v1.y * (1.0f + erff(v1.y * 0.70710678118654752f));
            }
            if (RES) {
                const float2 r0 = *(const float2*)(res + (size_t)mA * N + n);
                const float2 r1 = *(const float2*)(res + (size_t)mB * N + n);
                v0.x += r0.x; v0.y += r0.y;
                v1.x += r1.x; v1.y += r1.y;
            }
            if (OUTBF) {
                *(uint32_t*)(Cb + (size_t)mA * N + n) = packbf(v0.x, v0.y);
                *(uint32_t*)(Cb + (size_t)mB * N + n) = packbf(v1.x, v1.y);
            } else {
                *(float2*)(Cf + (size_t)mA * N + n) = v0;
                *(float2*)(Cf + (size_t)mB * N + n) = v1;
            }
        }
    }
}

// ---------------------------------------------------------------------------
// bf16 flash attention. grid=(SEQ/128, B*NH), 256 thr = 8 warps x 16 q-rows.
// S and P.V on m16n8k16 bf16 mma; P stays in registers (acc->A-frag identity).
// K/V double-buffered via cp.async.
// ---------------------------------------------------------------------------
__global__ __launch_bounds__(256, 2) void attn_mma(
    const __nv_bfloat16* __restrict__ qkv, __nv_bfloat16* __restrict__ out)
{
    extern __shared__ char smem[];
    const uint32_t sq = smem_u32(smem);           // Q: 128 rows
    const uint32_t skv = sq + 128 * GROWB;        // 2 KV stages

    const int bh = blockIdx.y;
    const int b = bh >> 4;
    const int h = bh & 15;
    const int q0 = blockIdx.x * AQ;
    const int tid = threadIdx.x;
    const int wid = tid >> 5;
    const int lane = tid & 31;
    const int g = lane >> 2;
    const int cg = lane & 3;
    const int wrow = wid * 16;
    const uint32_t lmrow = (lane & 15);
    const uint32_t lmsel = ((lane >> 4) & 1) * 16;

    const size_t base = (size_t)b * SEQ * 3 * ETOT;

    // Stage Q (uint4 = 8 bf16)
#pragma unroll
    for (int it = 0; it < 4; it++) {
        const int idx = tid + it * 256;
        const int r = idx >> 3, c = idx & 7;
        const uint4 v = *(const uint4*)(qkv + base + (size_t)(q0 + r) * (3 * ETOT) + h * HD + c * 8);
        *(uint4*)(smem + r * GROWB + c * 16) = v;
    }
    __syncthreads();

    // Persistent Q fragments (4 k16 steps)
    uint32_t qf[4][4];
#pragma unroll
    for (int ks = 0; ks < 4; ks++)
        ldm_x4(qf[ks], sq + (wrow + lmrow) * GROWB + ks * 32 + lmsel);

    // KV loader: row = tid>>2 (0..63), chunks (tid&3) and (tid&3)+4
    const int r2 = tid >> 2;
    const int c2 = tid & 3;
    const __nv_bfloat16* gkb = qkv + base + ETOT + h * HD + c2 * 8 + (size_t)r2 * (3 * ETOT);
    auto issueKV = [&](int st, int k0) {
        const uint32_t dK = skv + st * KV_STAGE + r2 * GROWB + c2 * 16;
        const uint32_t dV = dK + 64 * GROWB;
        const __nv_bfloat16* gk = gkb + (size_t)k0 * (3 * ETOT);
        cp16(dK, gk);
        cp16(dK + 64, gk + 32);
        cp16(dV, gk + ETOT);
        cp16(dV + 64, gk + ETOT + 32);
        asm volatile("cp.async.commit_group;");
    };

    float o[8][4];
#pragma unroll
    for (int nd = 0; nd < 8; nd++)
#pragma unroll
        for (int e = 0; e < 4; e++) o[nd][e] = 0.f;
    float m0 = -1e30f, m1 = -1e30f, l0 = 0.f, l1 = 0.f;

    issueKV(0, 0);

    const int NC = SEQ / AKV;
    for (int c = 0; c < NC; c++) {
        if (c + 1 < NC) {
            issueKV((c + 1) & 1, (c + 1) * AKV);
            asm volatile("cp.async.wait_group 1;");
        } else {
            asm volatile("cp.async.wait_group 0;");
        }
        __syncthreads();

        const uint32_t sK = skv + (c & 1) * KV_STAGE;
        const uint32_t sV = sK + 64 * GROWB;

        // S = Q @ K^T
        float s[8][4];
#pragma unroll
        for (int nj = 0; nj < 8; nj++)
#pragma unroll
            for (int e = 0; e < 4; e++) s[nj][e] = 0.f;
#pragma unroll
        for (int ks = 0; ks < 4; ks++) {
            uint32_t km[4][4];
#pragma unroll
            for (int p = 0; p < 4; p++)
                ldm_x4(km[p], sK + (p * 16 + lmrow) * GROWB + ks * 32 + lmsel);
#pragma unroll
            for (int nj = 0; nj < 8; nj++) {
                uint32_t bf[2] = { km[nj >> 1][nj & 1], km[nj >> 1][(nj & 1) + 2] };
                mma_bf16(s[nj], qf[ks], bf);
            }
        }

        // online softmax (rows g / g+8; quad over cg = lane bits 0,1)
        float mn0 = -1e30f, mn1 = -1e30f;
#pragma unroll
        for (int nj = 0; nj < 8; nj++) {
#pragma unroll
            for (int e = 0; e < 4; e++) s[nj][e] *= 0.125f;
            mn0 = fmaxf(mn0, fmaxf(s[nj][0], s[nj][1]));
            mn1 = fmaxf(mn1, fmaxf(s[nj][2], s[nj][3]));
        }
        mn0 = fmaxf(mn0, __shfl_xor_sync(0xffffffffu, mn0, 1));
        mn0 = fmaxf(mn0, __shfl_xor_sync(0xffffffffu, mn0, 2));
        mn1 = fmaxf(mn1, __shfl_xor_sync(0xffffffffu, mn1, 1));
        mn1 = fmaxf(mn1, __shfl_xor_sync(0xffffffffu, mn1, 2));
        const float mN0 = fmaxf(m0, mn0);
        const float mN1 = fmaxf(m1, mn1);
        const float c0 = __expf(m0 - mN0);
        const float c1 = __expf(m1 - mN1);
        m0 = mN0; m1 = mN1;
        float sum0 = 0.f, sum1 = 0.f;
#pragma unroll
        for (int nj = 0; nj < 8; nj++) {
            s[nj][0] = __expf(s[nj][0] - mN0);
            s[nj][1] = __expf(s[nj][1] - mN0);
            s[nj][2] = __expf(s[nj][2] - mN1);
            s[nj][3] = __expf(s[nj][3] - mN1);
            sum0 += s[nj][0] + s[nj][1];
            sum1 += s[nj][2] + s[nj][3];
        }
        sum0 += __shfl_xor_sync(0xffffffffu, sum0, 1);
        sum0 += __shfl_xor_sync(0xffffffffu, sum0, 2);
        sum1 += __shfl_xor_sync(0xffffffffu, sum1, 1);
        sum1 += __shfl_xor_sync(0xffffffffu, sum1, 2);
        l0 = l0 * c0 + sum0;
        l1 = l1 * c1 + sum1;
#pragma unroll
        for (int nd = 0; nd < 8; nd++) {
            o[nd][0] *= c0; o[nd][1] *= c0;
            o[nd][2] *= c1; o[nd][3] *= c1;
        }

        // O += P @ V : P packed from S accumulators (register-only)
#pragma unroll
        for (int ks2 = 0; ks2 < 4; ks2++) {
            uint32_t pf[4];
            pf[0] = packbf(s[2 * ks2][0],     s[2 * ks2][1]);
            pf[1] = packbf(s[2 * ks2][2],     s[2 * ks2][3]);
            pf[2] = packbf(s[2 * ks2 + 1][0], s[2 * ks2 + 1][1]);
            pf[3] = packbf(s[2 * ks2 + 1][2], s[2 * ks2 + 1][3]);
            uint32_t vm[4][4];
#pragma unroll
            for (int p = 0; p < 4; p++)
                ldm_x4_t(vm[p], sV + (ks2 * 16 + lmrow) * GROWB + p * 32 + lmsel);
#pragma unroll
            for (int nd = 0; nd < 8; nd++) {
                uint32_t bf[2] = { vm[nd >> 1][(nd & 1) * 2], vm[nd >> 1][(nd & 1) * 2 + 1] };
                mma_bf16(o[nd], pf, bf);
            }
        }
        __syncthreads();
    }

    // Epilogue: normalize, write bf16
    const float inv0 = 1.0f / l0;
    const float inv1 = 1.0f / l1;
    const int tokA = q0 + wrow + g;
    const int tokB = tokA + 8;
    const size_t rA = (size_t)(b * SEQ + tokA) * ETOT + h * HD;
    const size_t rB = (size_t)(b * SEQ + tokB) * ETOT + h * HD;
#pragma unroll
    for (int nd = 0; nd < 8; nd++) {
        const int n = nd * 8 + 2 * cg;
        *(uint32_t*)(out + rA + n) = packbf(o[nd][0] * inv0, o[nd][1] * inv0);
        *(uint32_t*)(out + rB + n) = packbf(o[nd][2] * inv1, o[nd][3] * inv1);
    }
}

// ---------------------------------------------------------------------------
// Host launcher
// ---------------------------------------------------------------------------
extern "C" void kernel_launch(void* const* d_in, const int* in_sizes, int n_in,
                              void* d_out, int out_size)
{
    const float* x     = (const float*)d_in[0];
    const float* qkv_w = (const float*)d_in[1];
    const float* fc_w  = (const float*)d_in[2];
    const float* fc_b  = (const float*)d_in[3];
    const float* ln1_g = (const float*)d_in[4];
    const float* ln1_b = (const float*)d_in[5];
    const float* ln2_g = (const float*)d_in[6];
    const float* ln2_b = (const float*)d_in[7];
    const float* w1    = (const float*)d_in[8];
    const float* b1    = (const float*)d_in[9];
    const float* w2    = (const float*)d_in[10];
    const float* b2    = (const float*)d_in[11];
    float* out = (float*)d_out;

    void *ph, *pq, *pa, *px2, *pm, *pwq, *pwf, *pw1, *pw2;
    cudaGetSymbolAddress(&ph,  g_h);
    cudaGetSymbolAddress(&pq,  g_qkv);
    cudaGetSymbolAddress(&pa,  g_attn);
    cudaGetSymbolAddress(&px2, g_x2);
    cudaGetSymbolAddress(&pm,  g_mid);
    cudaGetSymbolAddress(&pwq, g_wq);
    cudaGetSymbolAddress(&pwf, g_wf);
    cudaGetSymbolAddress(&pw1, g_w1);
    cudaGetSymbolAddress(&pw2, g_w2);
    __nv_bfloat16* h    = (__nv_bfloat16*)ph;
    __nv_bfloat16* qkvb = (__nv_bfloat16*)pq;
    __nv_bfloat16* attn = (__nv_bfloat16*)pa;
    float*         x2   = (float*)px2;
    __nv_bfloat16* mid  = (__nv_bfloat16*)pm;
    __nv_bfloat16* wq   = (__nv_bfloat16*)pwq;
    __nv_bfloat16* wf   = (__nv_bfloat16*)pwf;
    __nv_bfloat16* w1r  = (__nv_bfloat16*)pw1;
    __nv_bfloat16* w2r  = (__nv_bfloat16*)pw2;

    cudaFuncSetAttribute(bf_gemm<false, false, false, true>,
                         cudaFuncAttributeMaxDynamicSharedMemorySize, SMEM_GEMM);
    cudaFuncSetAttribute(bf_gemm<true, true, false, false>,
                         cudaFuncAttributeMaxDynamicSharedMemorySize, SMEM_GEMM);
    cudaFuncSetAttribute(bf_gemm<true, false, true, true>,
                         cudaFuncAttributeMaxDynamicSharedMemorySize, SMEM_GEMM);
    cudaFuncSetAttribute(attn_mma,
                         cudaFuncAttributeMaxDynamicSharedMemorySize, SMEM_ATTN);

    // 0. Convert all weights to bf16 (single launch)
    round_all<<<ROUND_BLOCKS, 256>>>(qkv_w, fc_w, w1, w2, wq, wf, w1r, w2r);

    // 1. h = LN1(x) -> bf16
    ln_kernel<<<NTOK, 256>>>(x, ln1_g, ln1_b, h);

    // 2. qkv = h @ qkv_w^T -> bf16
    bf_gemm<false, false, false, true>
        <<<dim3((3 * ETOT) / BN, NTOK / BM), 256, SMEM_GEMM>>>(
        h, wq, nullptr, nullptr, nullptr, qkvb, NTOK, 3 * ETOT, ETOT);

    // 3. attention -> bf16
    attn_mma<<<dim3(SEQ / AQ, 4 * NH), 256, SMEM_ATTN>>>(qkvb, attn);

    // 4. x2 = x + attn @ fc_w^T + fc_b -> fp32
    bf_gemm<true, true, false, false>
        <<<dim3(ETOT / BN, NTOK / BM), 256, SMEM_GEMM>>>(
        attn, wf, fc_b, x, x2, nullptr, NTOK, ETOT, ETOT);

    // 5. h = LN2(x2) -> bf16
    ln_kernel<<<NTOK, 256>>>(x2, ln2_g, ln2_b, h);

    // 6. mid = gelu(h @ w1^T + b1) -> bf16
    bf_gemm<true, false, true, true>
        <<<dim3(MLPD / BN, NTOK / BM), 256, SMEM_GEMM>>>(
        h, w1r, b1, nullptr, nullptr, mid, NTOK, MLPD, ETOT);

    // 7. out = x2 + mid @ w2^T + b2 -> fp32
    bf_gemm<true, true, false, false>
        <<<dim3(ETOT / BN, NTOK / BM), 256, SMEM_GEMM>>>(
        mid, w2r, b2, x2, out, nullptr, NTOK, ETOT, MLPD);
}

// round 13
// speedup vs baseline: 1.5599x; 1.0092x over previous
#include <cuda_runtime.h>
#include <cuda_bf16.h>
#include <math.h>
#include <stdint.h>

// Problem constants
#define ETOT 1024
#define NTOK 8192
#define SEQ  2048
#define NH   16
#define HD   64
#define MLPD 4096

// GEMM tile config (bf16 mma m16n8k16)
#define BM 128
#define BN 128
#define BK 64
#define GROWB 144                              // smem row stride bytes (64 bf16 + 16B pad)
#define G_STAGE (2 * 128 * GROWB)              // A+B per stage = 36864 B
#define GSTAGES 3
#define SMEM_GEMM (GSTAGES * G_STAGE)          // 110592 B

// Attention config
#define AQ 128
#define AKV 64
#define KV_STAGE (2 * 64 * GROWB)              // K+V per stage = 18432 B
#define KVSTAGES 3
#define SMEM_ATTN (128 * GROWB + KVSTAGES * KV_STAGE)  // 73728 B

#define LOG2E 1.4426950408889634f

// Scratch (allocation-free rule: __device__ globals)
__device__ __nv_bfloat16 g_h[NTOK * ETOT];
__device__ __nv_bfloat16 g_qkv[NTOK * 3 * ETOT];
__device__ __nv_bfloat16 g_attn[NTOK * ETOT];
__device__ float         g_x2[NTOK * ETOT];
__device__ __nv_bfloat16 g_mid[NTOK * MLPD];
__device__ __nv_bfloat16 g_wq[3 * ETOT * ETOT];
__device__ __nv_bfloat16 g_wf[ETOT * ETOT];
__device__ __nv_bfloat16 g_w1[MLPD * ETOT];
__device__ __nv_bfloat16 g_w2[ETOT * MLPD];

// ---------------------------------------------------------------------------
// Helpers
// ---------------------------------------------------------------------------
__device__ __forceinline__ uint32_t packbf(float lo, float hi) {
    __nv_bfloat162 t;
    t.x = __float2bfloat16_rn(lo);
    t.y = __float2bfloat16_rn(hi);
    return *reinterpret_cast<uint32_t*>(&t);
}

__device__ __forceinline__ void mma_bf16(float* d, const uint32_t* a,
                                         const uint32_t* b) {
    asm volatile(
        "mma.sync.aligned.m16n8k16.row.col.f32.bf16.bf16.f32 "
        "{%0,%1,%2,%3}, {%4,%5,%6,%7}, {%8,%9}, {%0,%1,%2,%3};"
        : "+f"(d[0]), "+f"(d[1]), "+f"(d[2]), "+f"(d[3])
        : "r"(a[0]), "r"(a[1]), "r"(a[2]), "r"(a[3]), "r"(b[0]), "r"(b[1]));
}

__device__ __forceinline__ void ldm_x4(uint32_t* r, uint32_t addr) {
    asm volatile("ldmatrix.sync.aligned.m8n8.x4.shared.b16 {%0,%1,%2,%3}, [%4];"
                 : "=r"(r[0]), "=r"(r[1]), "=r"(r[2]), "=r"(r[3]) : "r"(addr));
}

__device__ __forceinline__ void ldm_x4_t(uint32_t* r, uint32_t addr) {
    asm volatile("ldmatrix.sync.aligned.m8n8.x4.trans.shared.b16 {%0,%1,%2,%3}, [%4];"
                 : "=r"(r[0]), "=r"(r[1]), "=r"(r[2]), "=r"(r[3]) : "r"(addr));
}

__device__ __forceinline__ void cp16(uint32_t dst_smem, const void* src) {
    asm volatile("cp.async.cg.shared.global [%0], [%1], 16;"
                 :: "r"(dst_smem), "l"(src));
}

__device__ __forceinline__ uint32_t smem_u32(const void* p) {
    uint32_t a;
    asm("{ .reg .u64 t; cvta.to.shared.u64 t, %1; cvt.u32.u64 %0, t; }"
        : "=r"(a) : "l"(p));
    return a;
}

// ---------------------------------------------------------------------------
// Fused weight conversion fp32 -> bf16 (single launch, 4 segments of float4)
// ---------------------------------------------------------------------------
__global__ __launch_bounds__(256) void round_all(
    const float* __restrict__ qkv_w, const float* __restrict__ fc_w,
    const float* __restrict__ w1, const float* __restrict__ w2,
    __nv_bfloat16* __restrict__ owq, __nv_bfloat16* __restrict__ owf,
    __nv_bfloat16* __restrict__ ow1, __nv_bfloat16* __restrict__ ow2)
{
    int i = blockIdx.x * 256 + threadIdx.x;
    const float4* src;
    __nv_bfloat16* dst;
    if (i < 786432) {
        src = (const float4*)qkv_w; dst = owq;
    } else if (i < 786432 + 262144) {
        i -= 786432;
        src = (const float4*)fc_w; dst = owf;
    } else if (i < 786432 + 262144 + 1048576) {
        i -= 786432 + 262144;
        src = (const float4*)w1; dst = ow1;
    } else {
        i -= 786432 + 262144 + 1048576;
        src = (const float4*)w2; dst = ow2;
    }
    const float4 v = src[i];
    uint2 w;
    w.x = packbf(v.x, v.y);
    w.y = packbf(v.z, v.w);
    ((uint2*)dst)[i] = w;
}
#define ROUND_BLOCKS ((786432 + 262144 + 1048576 + 1048576) / 256)

// ---------------------------------------------------------------------------
// LayerNorm: fp32 in, bf16 out (feeds mma only)
// ---------------------------------------------------------------------------
__global__ __launch_bounds__(256) void ln_kernel(
    const float* __restrict__ x, const float* __restrict__ g,
    const float* __restrict__ b, __nv_bfloat16* __restrict__ out)
{
    const int row = blockIdx.x;
    const int tid = threadIdx.x;
    const float4 v = ((const float4*)(x + (long)row * ETOT))[tid];
    float s = v.x + v.y + v.z + v.w;
    float s2 = v.x * v.x + v.y * v.y + v.z * v.z + v.w * v.w;
#pragma unroll
    for (int o = 16; o; o >>= 1) {
        s  += __shfl_down_sync(0xffffffffu, s, o);
        s2 += __shfl_down_sync(0xffffffffu, s2, o);
    }
    __shared__ float sm[8], sm2[8];
    if ((tid & 31) == 0) { sm[tid >> 5] = s; sm2[tid >> 5] = s2; }
    __syncthreads();
    float ts = 0.f, ts2 = 0.f;
#pragma unroll
    for (int i = 0; i < 8; i++) { ts += sm[i]; ts2 += sm2[i]; }
    const float mu = ts * (1.0f / ETOT);
    const float var = ts2 * (1.0f / ETOT) - mu * mu;
    const float r = rsqrtf(var + 1e-5f);
    const float4 gv = ((const float4*)g)[tid];
    const float4 bv = ((const float4*)b)[tid];
    uint2 w;
    w.x = packbf((v.x - mu) * r * gv.x + bv.x, (v.y - mu) * r * gv.y + bv.y);
    w.y = packbf((v.z - mu) * r * gv.z + bv.z, (v.w - mu) * r * gv.w + bv.w);
    ((uint2*)(out + (long)row * ETOT))[tid] = w;
}

// ---------------------------------------------------------------------------
// bf16 GEMM: C[M,N] = A[M,K] @ W[N,K]^T (+bias)(+GELU)(+residual)
// BM=BN=128, BK=64, 3-stage cp.async, single __syncthreads per tile.
// ---------------------------------------------------------------------------
template <bool BIAS, bool RES, bool GELU, bool OUTBF>
__global__ __launch_bounds__(256, 2) void bf_gemm(
    const __nv_bfloat16* __restrict__ A, const __nv_bfloat16* __restrict__ W,
    const float* __restrict__ bias, const float* __restrict__ res,
    float* __restrict__ Cf, __nv_bfloat16* __restrict__ Cb,
    int M, int N, int K)
{
    extern __shared__ char smem[];
    const uint32_t sb = smem_u32(smem);

    const int tid = threadIdx.x;
    const int m0 = blockIdx.y * BM;
    const int n0 = blockIdx.x * BN;

    const int lrow = tid >> 1;
    const int lc4 = (tid & 1) * 4;
    const __nv_bfloat16* Ap = A + (size_t)(m0 + lrow) * K + lc4 * 8;
    const __nv_bfloat16* Wp = W + (size_t)(n0 + lrow) * K + lc4 * 8;
    const uint32_t dro = (uint32_t)(lrow * GROWB + lc4 * 16);

    const int wid = tid >> 5;
    const int lane = tid & 31;
    const int wm = (wid >> 2) * 64;
    const int wn = (wid & 3) * 32;
    const int g = lane >> 2;
    const int cg = lane & 3;
    const uint32_t lmrow = (lane & 15);
    const uint32_t lmsel = ((lane >> 4) & 1) * 16;

    float acc[4][4][4];
#pragma unroll
    for (int mi = 0; mi < 4; mi++)
#pragma unroll
        for (int nj = 0; nj < 4; nj++)
#pragma unroll
            for (int e = 0; e < 4; e++) acc[mi][nj][e] = 0.f;

    auto issue = [&](int st, int kt) {
        const uint32_t dA = sb + st * G_STAGE + dro;
        const uint32_t dB = dA + 128 * GROWB;
#pragma unroll
        for (int i = 0; i < 4; i++) {
            cp16(dA + i * 16, Ap + kt + i * 8);
            cp16(dB + i * 16, Wp + kt + i * 8);
        }
        asm volatile("cp.async.commit_group;");
    };

    const int T = K / BK;
    issue(0, 0);
    issue(1, BK);

    for (int t = 0; t < T; t++) {
        if (t + 1 < T) asm volatile("cp.async.wait_group 1;");
        else           asm volatile("cp.async.wait_group 0;");
        __syncthreads();

        if (t + 2 < T) issue((t + 2) % GSTAGES, (t + 2) * BK);

        const uint32_t sA = sb + (t % GSTAGES) * G_STAGE;
        const uint32_t sB = sA + 128 * GROWB;

#pragma unroll
        for (int ks = 0; ks < 4; ks++) {
            uint32_t af[4][4];
#pragma unroll
            for (int mi = 0; mi < 4; mi++)
                ldm_x4(af[mi], sA + (wm + mi * 16 + lmrow) * GROWB + ks * 32 + lmsel);
            uint32_t bm[2][4];
#pragma unroll
            for (int p = 0; p < 2; p++)
                ldm_x4(bm[p], sB + (wn + p * 16 + lmrow) * GROWB + ks * 32 + lmsel);
#pragma unroll
            for (int mi = 0; mi < 4; mi++)
#pragma unroll
                for (int nj = 0; nj < 4; nj++) {
                    uint32_t bf[2] = { bm[nj >> 1][nj & 1], bm[nj >> 1][(nj & 1) + 2] };
                    mma_bf16(acc[mi][nj], af[mi], bf);
                }
        }
    }

    // Epilogue
#pragma unroll
    for (int mi = 0; mi < 4; mi++) {
        const int mA = m0 + wm + mi * 16 + g;
        const int mB = mA + 8;
#pragma unroll
        for (int nj = 0; nj < 4; nj++) {
            const int n = n0 + wn + nj * 8 + 2 * cg;
            float2 v0 = make_float2(acc[mi][nj][0], acc[mi][nj][1]);
            float2 v1 = make_float2(acc[mi][nj][2], acc[mi][nj][3]);
            if (BIAS) {
                const float b0 = bias[n], b1 = bias[n + 1];
                v0.x += b0; v0.y += b1;
                v1.x += b0; v1.y += b1;
            }
            if (GELU) {
                v0.x = 0.5f * v0.x * (1.0f + erff(v0.x * 0.70710678118654752f));
                v0.y = 0.5f * v0.y * (1.0f + erff(v0.y * 0.70710678118654752f));
                v1.x = 0.5f * v1.x * (1.0f + erff(v1.x * 0.70710678118654752f));
                v1.y = 0.5f * v1.y * (1.0f + erff(v1.y * 0.70710678118654752f));
            }
            if (RES) {
                const float2 r0 = *(const float2*)(res + (size_t)mA * N + n);
                const float2 r1 = *(const float2*)(res + (size_t)mB * N + n);
                v0.x += r0.x; v0.y += r0.y;
                v1.x += r1.x; v1.y += r1.y;
            }
            if (OUTBF) {
                *(uint32_t*)(Cb + (size_t)mA * N + n) = packbf(v0.x, v0.y);
                *(uint32_t*)(Cb + (size_t)mB * N + n) = packbf(v1.x, v1.y);
            } else {
                *(float2*)(Cf + (size_t)mA * N + n) = v0;
                *(float2*)(Cf + (size_t)mB * N + n) = v1;
            }
        }
    }
}

// ---------------------------------------------------------------------------
// bf16 flash attention, 3-stage KV ring, exp2-domain softmax.
// grid=(SEQ/128, B*NH), 256 thr = 8 warps x 16 q-rows.
// ---------------------------------------------------------------------------
__global__ __launch_bounds__(256, 2) void attn_mma(
    const __nv_bfloat16* __restrict__ qkv, __nv_bfloat16* __restrict__ out)
{
    extern __shared__ char smem[];
    const uint32_t sq = smem_u32(smem);
    const uint32_t skv = sq + 128 * GROWB;

    const int bh = blockIdx.y;
    const int b = bh >> 4;
    const int h = bh & 15;
    const int q0 = blockIdx.x * AQ;
    const int tid = threadIdx.x;
    const int wid = tid >> 5;
    const int lane = tid & 31;
    const int g = lane >> 2;
    const int cg = lane & 3;
    const int wrow = wid * 16;
    const uint32_t lmrow = (lane & 15);
    const uint32_t lmsel = ((lane >> 4) & 1) * 16;

    const size_t base = (size_t)b * SEQ * 3 * ETOT;

    // Stage Q
#pragma unroll
    for (int it = 0; it < 4; it++) {
        const int idx = tid + it * 256;
        const int r = idx >> 3, c = idx & 7;
        const uint4 v = *(const uint4*)(qkv + base + (size_t)(q0 + r) * (3 * ETOT) + h * HD + c * 8);
        *(uint4*)(smem + r * GROWB + c * 16) = v;
    }

    // KV loader
    const int r2 = tid >> 2;
    const int c2 = tid & 3;
    const __nv_bfloat16* gkb = qkv + base + ETOT + h * HD + c2 * 8 + (size_t)r2 * (3 * ETOT);
    auto issueKV = [&](int st, int k0) {
        const uint32_t dK = skv + st * KV_STAGE + r2 * GROWB + c2 * 16;
        const uint32_t dV = dK + 64 * GROWB;
        const __nv_bfloat16* gk = gkb + (size_t)k0 * (3 * ETOT);
        cp16(dK, gk);
        cp16(dK + 64, gk + 32);
        cp16(dV, gk + ETOT);
        cp16(dV + 64, gk + ETOT + 32);
        asm volatile("cp.async.commit_group;");
    };

    issueKV(0, 0);
    issueKV(1, AKV);
    __syncthreads();

    // Persistent Q fragments
    uint32_t qf[4][4];
#pragma unroll
    for (int ks = 0; ks < 4; ks++)
        ldm_x4(qf[ks], sq + (wrow + lmrow) * GROWB + ks * 32 + lmsel);

    float o[8][4];
#pragma unroll
    for (int nd = 0; nd < 8; nd++)
#pragma unroll
        for (int e = 0; e < 4; e++) o[nd][e] = 0.f;
    float m0 = -1e30f, m1 = -1e30f, l0 = 0.f, l1 = 0.f;

    const float SSCALE = 0.125f * LOG2E;

    const int NC = SEQ / AKV;
    for (int c = 0; c < NC; c++) {
        if (c + 1 < NC) asm volatile("cp.async.wait_group 1;");
        else            asm volatile("cp.async.wait_group 0;");
        __syncthreads();

        if (c + 2 < NC) issueKV((c + 2) % KVSTAGES, (c + 2) * AKV);

        const uint32_t sK = skv + (c % KVSTAGES) * KV_STAGE;
        const uint32_t sV = sK + 64 * GROWB;

        // S = Q @ K^T
        float s[8][4];
#pragma unroll
        for (int nj = 0; nj < 8; nj++)
#pragma unroll
            for (int e = 0; e < 4; e++) s[nj][e] = 0.f;
#pragma unroll
        for (int ks = 0; ks < 4; ks++) {
            uint32_t km[4][4];
#pragma unroll
            for (int p = 0; p < 4; p++)
                ldm_x4(km[p], sK + (p * 16 + lmrow) * GROWB + ks * 32 + lmsel);
#pragma unroll
            for (int nj = 0; nj < 8; nj++) {
                uint32_t bf[2] = { km[nj >> 1][nj & 1], km[nj >> 1][(nj & 1) + 2] };
                mma_bf16(s[nj], qf[ks], bf);
            }
        }

        // online softmax, base-2 domain (s *= 0.125*log2e; exp2)
        float mn0 = -1e30f, mn1 = -1e30f;
#pragma unroll
        for (int nj = 0; nj < 8; nj++) {
#pragma unroll
            for (int e = 0; e < 4; e++) s[nj][e] *= SSCALE;
            mn0 = fmaxf(mn0, fmaxf(s[nj][0], s[nj][1]));
            mn1 = fmaxf(mn1, fmaxf(s[nj][2], s[nj][3]));
        }
        mn0 = fmaxf(mn0, __shfl_xor_sync(0xffffffffu, mn0, 1));
        mn0 = fmaxf(mn0, __shfl_xor_sync(0xffffffffu, mn0, 2));
        mn1 = fmaxf(mn1, __shfl_xor_sync(0xffffffffu, mn1, 1));
        mn1 = fmaxf(mn1, __shfl_xor_sync(0xffffffffu, mn1, 2));
        const float mN0 = fmaxf(m0, mn0);
        const float mN1 = fmaxf(m1, mn1);
        const float c0 = exp2f(m0 - mN0);
        const float c1 = exp2f(m1 - mN1);
        m0 = mN0; m1 = mN1;
        float sum0 = 0.f, sum1 = 0.f;
#pragma unroll
        for (int nj = 0; nj < 8; nj++) {
            s[nj][0] = exp2f(s[nj][0] - mN0);
            s[nj][1] = exp2f(s[nj][1] - mN0);
            s[nj][2] = exp2f(s[nj][2] - mN1);
            s[nj][3] = exp2f(s[nj][3] - mN1);
            sum0 += s[nj][0] + s[nj][1];
            sum1 += s[nj][2] + s[nj][3];
        }
        sum0 += __shfl_xor_sync(0xffffffffu, sum0, 1);
        sum0 += __shfl_xor_sync(0xffffffffu, sum0, 2);
        sum1 += __shfl_xor_sync(0xffffffffu, sum1, 1);
        sum1 += __shfl_xor_sync(0xffffffffu, sum1, 2);
        l0 = l0 * c0 + sum0;
        l1 = l1 * c1 + sum1;
#pragma unroll
        for (int nd = 0; nd < 8; nd++) {
            o[nd][0] *= c0; o[nd][1] *= c0;
            o[nd][2] *= c1; o[nd][3] *= c1;
        }

        // O += P @ V  (P packed from S accumulators, register-only)
#pragma unroll
        for (int ks2 = 0; ks2 < 4; ks2++) {
            uint32_t pf[4];
            pf[0] = packbf(s[2 * ks2][0],     s[2 * ks2][1]);
            pf[1] = packbf(s[2 * ks2][2],     s[2 * ks2][3]);
            pf[2] = packbf(s[2 * ks2 + 1][0], s[2 * ks2 + 1][1]);
            pf[3] = packbf(s[2 * ks2 + 1][2], s[2 * ks2 + 1][3]);
            uint32_t vm[4][4];
#pragma unroll
            for (int p = 0; p < 4; p++)
                ldm_x4_t(vm[p], sV + (ks2 * 16 + lmrow) * GROWB + p * 32 + lmsel);
#pragma unroll
            for (int nd = 0; nd < 8; nd++) {
                uint32_t bf[2] = { vm[nd >> 1][(nd & 1) * 2], vm[nd >> 1][(nd & 1) * 2 + 1] };
                mma_bf16(o[nd], pf, bf);
            }
        }
    }

    // Epilogue: normalize, write bf16
    const float inv0 = 1.0f / l0;
    const float inv1 = 1.0f / l1;
    const int tokA = q0 + wrow + g;
    const int tokB = tokA + 8;
    const size_t rA = (size_t)(b * SEQ + tokA) * ETOT + h * HD;
    const size_t rB = (size_t)(b * SEQ + tokB) * ETOT + h * HD;
#pragma unroll
    for (int nd = 0; nd < 8; nd++) {
        const int n = nd * 8 + 2 * cg;
        *(uint32_t*)(out + rA + n) = packbf(o[nd][0] * inv0, o[nd][1] * inv0);
        *(uint32_t*)(out + rB + n) = packbf(o[nd][2] * inv1, o[nd][3] * inv1);
    }
}

// ---------------------------------------------------------------------------
// Host launcher
// ---------------------------------------------------------------------------
extern "C" void kernel_launch(void* const* d_in, const int* in_sizes, int n_in,
                              void* d_out, int out_size)
{
    const float* x     = (const float*)d_in[0];
    const float* qkv_w = (const float*)d_in[1];
    const float* fc_w  = (const float*)d_in[2];
    const float* fc_b  = (const float*)d_in[3];
    const float* ln1_g = (const float*)d_in[4];
    const float* ln1_b = (const float*)d_in[5];
    const float* ln2_g = (const float*)d_in[6];
    const float* ln2_b = (const float*)d_in[7];
    const float* w1    = (const float*)d_in[8];
    const float* b1    = (const float*)d_in[9];
    const float* w2    = (const float*)d_in[10];
    const float* b2    = (const float*)d_in[11];
    float* out = (float*)d_out;

    void *ph, *pq, *pa, *px2, *pm, *pwq, *pwf, *pw1, *pw2;
    cudaGetSymbolAddress(&ph,  g_h);
    cudaGetSymbolAddress(&pq,  g_qkv);
    cudaGetSymbolAddress(&pa,  g_attn);
    cudaGetSymbolAddress(&px2, g_x2);
    cudaGetSymbolAddress(&pm,  g_mid);
    cudaGetSymbolAddress(&pwq, g_wq);
    cudaGetSymbolAddress(&pwf, g_wf);
    cudaGetSymbolAddress(&pw1, g_w1);
    cudaGetSymbolAddress(&pw2, g_w2);
    __nv_bfloat16* h    = (__nv_bfloat16*)ph;
    __nv_bfloat16* qkvb = (__nv_bfloat16*)pq;
    __nv_bfloat16* attn = (__nv_bfloat16*)pa;
    float*         x2   = (float*)px2;
    __nv_bfloat16* mid  = (__nv_bfloat16*)pm;
    __nv_bfloat16* wq   = (__nv_bfloat16*)pwq;
    __nv_bfloat16* wf   = (__nv_bfloat16*)pwf;
    __nv_bfloat16* w1r  = (__nv_bfloat16*)pw1;
    __nv_bfloat16* w2r  = (__nv_bfloat16*)pw2;

    cudaFuncSetAttribute(bf_gemm<false, false, false, true>,
                         cudaFuncAttributeMaxDynamicSharedMemorySize, SMEM_GEMM);
    cudaFuncSetAttribute(bf_gemm<true, true, false, false>,
                         cudaFuncAttributeMaxDynamicSharedMemorySize, SMEM_GEMM);
    cudaFuncSetAttribute(bf_gemm<true, false, true, true>,
                         cudaFuncAttributeMaxDynamicSharedMemorySize, SMEM_GEMM);
    cudaFuncSetAttribute(attn_mma,
                         cudaFuncAttributeMaxDynamicSharedMemorySize, SMEM_ATTN);

    // 0. Convert all weights to bf16 (single launch)
    round_all<<<ROUND_BLOCKS, 256>>>(qkv_w, fc_w, w1, w2, wq, wf, w1r, w2r);

    // 1. h = LN1(x) -> bf16
    ln_kernel<<<NTOK, 256>>>(x, ln1_g, ln1_b, h);

    // 2. qkv = h @ qkv_w^T -> bf16
    bf_gemm<false, false, false, true>
        <<<dim3((3 * ETOT) / BN, NTOK / BM), 256, SMEM_GEMM>>>(
        h, wq, nullptr, nullptr, nullptr, qkvb, NTOK, 3 * ETOT, ETOT);

    // 3. attention -> bf16
    attn_mma<<<dim3(SEQ / AQ, 4 * NH), 256, SMEM_ATTN>>>(qkvb, attn);

    // 4. x2 = x + attn @ fc_w^T + fc_b -> fp32
    bf_gemm<true, true, false, false>
        <<<dim3(ETOT / BN, NTOK / BM), 256, SMEM_GEMM>>>(
        attn, wf, fc_b, x, x2, nullptr, NTOK, ETOT, ETOT);

    // 5. h = LN2(x2) -> bf16
    ln_kernel<<<NTOK, 256>>>(x2, ln2_g, ln2_b, h);

    // 6. mid = gelu(h @ w1^T + b1) -> bf16
    bf_gemm<true, false, true, true>
        <<<dim3(MLPD / BN, NTOK / BM), 256, SMEM_GEMM>>>(
        h, w1r, b1, nullptr, nullptr, mid, NTOK, MLPD, ETOT);

    // 7. out = x2 + mid @ w2^T + b2 -> fp32
    bf_gemm<true, true, false, false>
        <<<dim3(ETOT / BN, NTOK / BM), 256, SMEM_GEMM>>>(
        mid, w2r, b2, x2, out, nullptr, NTOK, ETOT, MLPD);
}

// round 14
// speedup vs baseline: 1.9036x; 1.2204x over previous
#include <cuda_runtime.h>
#include <cuda_bf16.h>
#include <math.h>
#include <stdint.h>

// Problem constants
#define ETOT 1024
#define NTOK 8192
#define SEQ  2048
#define NH   16
#define HD   64
#define MLPD 4096

#define GROWB 144                              // smem row stride bytes (64 bf16 + 16B pad)
#define GSTAGES 3

// Attention config
#define AQ 128
#define AKV 64
#define KV_STAGE (2 * 64 * GROWB)
#define KVSTAGES 3
#define SMEM_ATTN (128 * GROWB + KVSTAGES * KV_STAGE)  // 73728 B

#define LOG2E 1.4426950408889634f

// Scratch (allocation-free rule: __device__ globals)
__device__ __nv_bfloat16 g_h[NTOK * ETOT];
__device__ __nv_bfloat16 g_qkv[NTOK * 3 * ETOT];
__device__ __nv_bfloat16 g_attn[NTOK * ETOT];
__device__ float         g_x2[NTOK * ETOT];
__device__ __nv_bfloat16 g_mid[NTOK * MLPD];
__device__ __nv_bfloat16 g_wq[3 * ETOT * ETOT];
__device__ __nv_bfloat16 g_wf[ETOT * ETOT];
__device__ __nv_bfloat16 g_w1[MLPD * ETOT];
__device__ __nv_bfloat16 g_w2[ETOT * MLPD];

// ---------------------------------------------------------------------------
// Helpers
// ---------------------------------------------------------------------------
__device__ __forceinline__ uint32_t packbf(float lo, float hi) {
    __nv_bfloat162 t;
    t.x = __float2bfloat16_rn(lo);
    t.y = __float2bfloat16_rn(hi);
    return *reinterpret_cast<uint32_t*>(&t);
}

__device__ __forceinline__ void mma_bf16(float* d, const uint32_t* a,
                                         const uint32_t* b) {
    asm volatile(
        "mma.sync.aligned.m16n8k16.row.col.f32.bf16.bf16.f32 "
        "{%0,%1,%2,%3}, {%4,%5,%6,%7}, {%8,%9}, {%0,%1,%2,%3};"
        : "+f"(d[0]), "+f"(d[1]), "+f"(d[2]), "+f"(d[3])
        : "r"(a[0]), "r"(a[1]), "r"(a[2]), "r"(a[3]), "r"(b[0]), "r"(b[1]));
}

__device__ __forceinline__ void ldm_x4(uint32_t* r, uint32_t addr) {
    asm volatile("ldmatrix.sync.aligned.m8n8.x4.shared.b16 {%0,%1,%2,%3}, [%4];"
                 : "=r"(r[0]), "=r"(r[1]), "=r"(r[2]), "=r"(r[3]) : "r"(addr));
}

__device__ __forceinline__ void ldm_x4_t(uint32_t* r, uint32_t addr) {
    asm volatile("ldmatrix.sync.aligned.m8n8.x4.trans.shared.b16 {%0,%1,%2,%3}, [%4];"
                 : "=r"(r[0]), "=r"(r[1]), "=r"(r[2]), "=r"(r[3]) : "r"(addr));
}

__device__ __forceinline__ void cp16(uint32_t dst_smem, const void* src) {
    asm volatile("cp.async.cg.shared.global [%0], [%1], 16;"
                 :: "r"(dst_smem), "l"(src));
}

__device__ __forceinline__ uint32_t smem_u32(const void* p) {
    uint32_t a;
    asm("{ .reg .u64 t; cvta.to.shared.u64 t, %1; cvt.u32.u64 %0, t; }"
        : "=r"(a) : "l"(p));
    return a;
}

// ---------------------------------------------------------------------------
// Fused weight conversion fp32 -> bf16 (single launch, 4 segments of float4)
// ---------------------------------------------------------------------------
__global__ __launch_bounds__(256) void round_all(
    const float* __restrict__ qkv_w, const float* __restrict__ fc_w,
    const float* __restrict__ w1, const float* __restrict__ w2,
    __nv_bfloat16* __restrict__ owq, __nv_bfloat16* __restrict__ owf,
    __nv_bfloat16* __restrict__ ow1, __nv_bfloat16* __restrict__ ow2)
{
    int i = blockIdx.x * 256 + threadIdx.x;
    const float4* src;
    __nv_bfloat16* dst;
    if (i < 786432) {
        src = (const float4*)qkv_w; dst = owq;
    } else if (i < 786432 + 262144) {
        i -= 786432;
        src = (const float4*)fc_w; dst = owf;
    } else if (i < 786432 + 262144 + 1048576) {
        i -= 786432 + 262144;
        src = (const float4*)w1; dst = ow1;
    } else {
        i -= 786432 + 262144 + 1048576;
        src = (const float4*)w2; dst = ow2;
    }
    const float4 v = src[i];
    uint2 w;
    w.x = packbf(v.x, v.y);
    w.y = packbf(v.z, v.w);
    ((uint2*)dst)[i] = w;
}
#define ROUND_BLOCKS ((786432 + 262144 + 1048576 + 1048576) / 256)

// ---------------------------------------------------------------------------
// LayerNorm: fp32 in, bf16 out
// ---------------------------------------------------------------------------
__global__ __launch_bounds__(256) void ln_kernel(
    const float* __restrict__ x, const float* __restrict__ g,
    const float* __restrict__ b, __nv_bfloat16* __restrict__ out)
{
    const int row = blockIdx.x;
    const int tid = threadIdx.x;
    const float4 v = ((const float4*)(x + (long)row * ETOT))[tid];
    float s = v.x + v.y + v.z + v.w;
    float s2 = v.x * v.x + v.y * v.y + v.z * v.z + v.w * v.w;
#pragma unroll
    for (int o = 16; o; o >>= 1) {
        s  += __shfl_down_sync(0xffffffffu, s, o);
        s2 += __shfl_down_sync(0xffffffffu, s2, o);
    }
    __shared__ float sm[8], sm2[8];
    if ((tid & 31) == 0) { sm[tid >> 5] = s; sm2[tid >> 5] = s2; }
    __syncthreads();
    float ts = 0.f, ts2 = 0.f;
#pragma unroll
    for (int i = 0; i < 8; i++) { ts += sm[i]; ts2 += sm2[i]; }
    const float mu = ts * (1.0f / ETOT);
    const float var = ts2 * (1.0f / ETOT) - mu * mu;
    const float r = rsqrtf(var + 1e-5f);
    const float4 gv = ((const float4*)g)[tid];
    const float4 bv = ((const float4*)b)[tid];
    uint2 w;
    w.x = packbf((v.x - mu) * r * gv.x + bv.x, (v.y - mu) * r * gv.y + bv.y);
    w.y = packbf((v.z - mu) * r * gv.z + bv.z, (v.w - mu) * r * gv.w + bv.w);
    ((uint2*)(out + (long)row * ETOT))[tid] = w;
}

// ---------------------------------------------------------------------------
// bf16 GEMM: C[M,N] = A[M,K] @ W[N,K]^T (+bias)(+GELU)(+residual)
// Template NJ = warp n-fragments: NJ=4 -> 128x128 tile (2 CTAs/SM),
//                                 NJ=8 -> 128x256 tile, 64x64 warp (1 CTA/SM).
// 3-stage cp.async, single __syncthreads per tile.
// ---------------------------------------------------------------------------
template <int NJ, bool BIAS, bool RES, bool GELU, bool OUTBF>
__global__ __launch_bounds__(256, (NJ == 4) ? 2 : 1) void bf_gemm(
    const __nv_bfloat16* __restrict__ A, const __nv_bfloat16* __restrict__ W,
    const float* __restrict__ bias, const float* __restrict__ res,
    float* __restrict__ Cf, __nv_bfloat16* __restrict__ Cb,
    int M, int N, int K)
{
    constexpr int BNRows = NJ * 32;                 // B tile rows
    constexpr int STAGE = (128 + BNRows) * GROWB;   // bytes per stage

    extern __shared__ char smem[];
    const uint32_t sb = smem_u32(smem);

    const int tid = threadIdx.x;
    const int m0 = blockIdx.y * 128;
    const int n0 = blockIdx.x * (NJ * 32);

    const int wid = tid >> 5;
    const int lane = tid & 31;
    const int wm = (wid >> 2) * 64;
    const int wn = (wid & 3) * (NJ * 8);
    const int g = lane >> 2;
    const int cg = lane & 3;
    const uint32_t lmrow = (lane & 15);
    const uint32_t lmsel = ((lane >> 4) & 1) * 16;

    float acc[4][NJ][4];
#pragma unroll
    for (int mi = 0; mi < 4; mi++)
#pragma unroll
        for (int nj = 0; nj < NJ; nj++)
#pragma unroll
            for (int e = 0; e < 4; e++) acc[mi][nj][e] = 0.f;

    // Loaders: idx -> (row = idx>>3, 16B chunk = idx&7); A 1024 cp16, B NJ*256 cp16
    auto issue = [&](int st, int kt) {
        const uint32_t dA = sb + st * STAGE;
        const uint32_t dB = dA + 128 * GROWB;
#pragma unroll
        for (int j = 0; j < 4; j++) {
            const int idx = tid + j * 256;
            const int r = idx >> 3, c = idx & 7;
            cp16(dA + r * GROWB + c * 16, A + (size_t)(m0 + r) * K + kt + c * 8);
        }
#pragma unroll
        for (int j = 0; j < NJ; j++) {
            const int idx = tid + j * 256;
            const int r = idx >> 3, c = idx & 7;
            cp16(dB + r * GROWB + c * 16, W + (size_t)(n0 + r) * K + kt + c * 8);
        }
        asm volatile("cp.async.commit_group;");
    };

    const int T = K / 64;
    issue(0, 0);
    issue(1, 64);

    for (int t = 0; t < T; t++) {
        if (t + 1 < T) asm volatile("cp.async.wait_group 1;");
        else           asm volatile("cp.async.wait_group 0;");
        __syncthreads();

        if (t + 2 < T) issue((t + 2) % GSTAGES, (t + 2) * 64);

        const uint32_t sA = sb + (t % GSTAGES) * STAGE;
        const uint32_t sB = sA + 128 * GROWB;

#pragma unroll
        for (int ks = 0; ks < 4; ks++) {
            uint32_t af[4][4];
#pragma unroll
            for (int mi = 0; mi < 4; mi++)
                ldm_x4(af[mi], sA + (wm + mi * 16 + lmrow) * GROWB + ks * 32 + lmsel);
            uint32_t bm[NJ / 2][4];
#pragma unroll
            for (int p = 0; p < NJ / 2; p++)
                ldm_x4(bm[p], sB + (wn + p * 16 + lmrow) * GROWB + ks * 32 + lmsel);
#pragma unroll
            for (int mi = 0; mi < 4; mi++)
#pragma unroll
                for (int nj = 0; nj < NJ; nj++) {
                    uint32_t bf[2] = { bm[nj >> 1][nj & 1], bm[nj >> 1][(nj & 1) + 2] };
                    mma_bf16(acc[mi][nj], af[mi], bf);
                }
        }
    }

    // Epilogue
#pragma unroll
    for (int mi = 0; mi < 4; mi++) {
        const int mA = m0 + wm + mi * 16 + g;
        const int mB = mA + 8;
#pragma unroll
        for (int nj = 0; nj < NJ; nj++) {
            const int n = n0 + wn + nj * 8 + 2 * cg;
            float2 v0 = make_float2(acc[mi][nj][0], acc[mi][nj][1]);
            float2 v1 = make_float2(acc[mi][nj][2], acc[mi][nj][3]);
            if (BIAS) {
                const float b0 = bias[n], b1 = bias[n + 1];
                v0.x += b0; v0.y += b1;
                v1.x += b0; v1.y += b1;
            }
            if (GELU) {
                v0.x = 0.5f * v0.x * (1.0f + erff(v0.x * 0.70710678118654752f));
                v0.y = 0.5f * v0.y * (1.0f + erff(v0.y * 0.70710678118654752f));
                v1.x = 0.5f * v1.x * (1.0f + erff(v1.x * 0.70710678118654752f));
                v1.y = 0.5f * v1.y * (1.0f + erff(v1.y * 0.70710678118654752f));
            }
            if (RES) {
                const float2 r0 = *(const float2*)(res + (size_t)mA * N + n);
                const float2 r1 = *(const float2*)(res + (size_t)mB * N + n);
                v0.x += r0.x; v0.y += r0.y;
                v1.x += r1.x; v1.y += r1.y;
            }
            if (OUTBF) {
                *(uint32_t*)(Cb + (size_t)mA * N + n) = packbf(v0.x, v0.y);
                *(uint32_t*)(Cb + (size_t)mB * N + n) = packbf(v1.x, v1.y);
            } else {
                *(float2*)(Cf + (size_t)mA * N + n) = v0;
                *(float2*)(Cf + (size_t)mB * N + n) = v1;
            }
        }
    }
}

#define SMEM_G4 (GSTAGES * (128 + 128) * GROWB)   // 110592
#define SMEM_G8 (GSTAGES * (128 + 256) * GROWB)   // 165888

// ---------------------------------------------------------------------------
// bf16 flash attention (unchanged from R13)
// ---------------------------------------------------------------------------
__global__ __launch_bounds__(256, 2) void attn_mma(
    const __nv_bfloat16* __restrict__ qkv, __nv_bfloat16* __restrict__ out)
{
    extern __shared__ char smem[];
    const uint32_t sq = smem_u32(smem);
    const uint32_t skv = sq + 128 * GROWB;

    const int bh = blockIdx.y;
    const int b = bh >> 4;
    const int h = bh & 15;
    const int q0 = blockIdx.x * AQ;
    const int tid = threadIdx.x;
    const int wid = tid >> 5;
    const int lane = tid & 31;
    const int g = lane >> 2;
    const int cg = lane & 3;
    const int wrow = wid * 16;
    const uint32_t lmrow = (lane & 15);
    const uint32_t lmsel = ((lane >> 4) & 1) * 16;

    const size_t base = (size_t)b * SEQ * 3 * ETOT;

#pragma unroll
    for (int it = 0; it < 4; it++) {
        const int idx = tid + it * 256;
        const int r = idx >> 3, c = idx & 7;
        const uint4 v = *(const uint4*)(qkv + base + (size_t)(q0 + r) * (3 * ETOT) + h * HD + c * 8);
        *(uint4*)(smem + r * GROWB + c * 16) = v;
    }

    const int r2 = tid >> 2;
    const int c2 = tid & 3;
    const __nv_bfloat16* gkb = qkv + base + ETOT + h * HD + c2 * 8 + (size_t)r2 * (3 * ETOT);
    auto issueKV = [&](int st, int k0) {
        const uint32_t dK = skv + st * KV_STAGE + r2 * GROWB + c2 * 16;
        const uint32_t dV = dK + 64 * GROWB;
        const __nv_bfloat16* gk = gkb + (size_t)k0 * (3 * ETOT);
        cp16(dK, gk);
        cp16(dK + 64, gk + 32);
        cp16(dV, gk + ETOT);
        cp16(dV + 64, gk + ETOT + 32);
        asm volatile("cp.async.commit_group;");
    };

    issueKV(0, 0);
    issueKV(1, AKV);
    __syncthreads();

    uint32_t qf[4][4];
#pragma unroll
    for (int ks = 0; ks < 4; ks++)
        ldm_x4(qf[ks], sq + (wrow + lmrow) * GROWB + ks * 32 + lmsel);

    float o[8][4];
#pragma unroll
    for (int nd = 0; nd < 8; nd++)
#pragma unroll
        for (int e = 0; e < 4; e++) o[nd][e] = 0.f;
    float m0 = -1e30f, m1 = -1e30f, l0 = 0.f, l1 = 0.f;

    const float SSCALE = 0.125f * LOG2E;

    const int NC = SEQ / AKV;
    for (int c = 0; c < NC; c++) {
        if (c + 1 < NC) asm volatile("cp.async.wait_group 1;");
        else            asm volatile("cp.async.wait_group 0;");
        __syncthreads();

        if (c + 2 < NC) issueKV((c + 2) % KVSTAGES, (c + 2) * AKV);

        const uint32_t sK = skv + (c % KVSTAGES) * KV_STAGE;
        const uint32_t sV = sK + 64 * GROWB;

        float s[8][4];
#pragma unroll
        for (int nj = 0; nj < 8; nj++)
#pragma unroll
            for (int e = 0; e < 4; e++) s[nj][e] = 0.f;
#pragma unroll
        for (int ks = 0; ks < 4; ks++) {
            uint32_t km[4][4];
#pragma unroll
            for (int p = 0; p < 4; p++)
                ldm_x4(km[p], sK + (p * 16 + lmrow) * GROWB + ks * 32 + lmsel);
#pragma unroll
            for (int nj = 0; nj < 8; nj++) {
                uint32_t bf[2] = { km[nj >> 1][nj & 1], km[nj >> 1][(nj & 1) + 2] };
                mma_bf16(s[nj], qf[ks], bf);
            }
        }

        float mn0 = -1e30f, mn1 = -1e30f;
#pragma unroll
        for (int nj = 0; nj < 8; nj++) {
#pragma unroll
            for (int e = 0; e < 4; e++) s[nj][e] *= SSCALE;
            mn0 = fmaxf(mn0, fmaxf(s[nj][0], s[nj][1]));
            mn1 = fmaxf(mn1, fmaxf(s[nj][2], s[nj][3]));
        }
        mn0 = fmaxf(mn0, __shfl_xor_sync(0xffffffffu, mn0, 1));
        mn0 = fmaxf(mn0, __shfl_xor_sync(0xffffffffu, mn0, 2));
        mn1 = fmaxf(mn1, __shfl_xor_sync(0xffffffffu, mn1, 1));
        mn1 = fmaxf(mn1, __shfl_xor_sync(0xffffffffu, mn1, 2));
        const float mN0 = fmaxf(m0, mn0);
        const float mN1 = fmaxf(m1, mn1);
        const float c0 = exp2f(m0 - mN0);
        const float c1 = exp2f(m1 - mN1);
        m0 = mN0; m1 = mN1;
        float sum0 = 0.f, sum1 = 0.f;
#pragma unroll
        for (int nj = 0; nj < 8; nj++) {
            s[nj][0] = exp2f(s[nj][0] - mN0);
            s[nj][1] = exp2f(s[nj][1] - mN0);
            s[nj][2] = exp2f(s[nj][2] - mN1);
            s[nj][3] = exp2f(s[nj][3] - mN1);
            sum0 += s[nj][0] + s[nj][1];
            sum1 += s[nj][2] + s[nj][3];
        }
        sum0 += __shfl_xor_sync(0xffffffffu, sum0, 1);
        sum0 += __shfl_xor_sync(0xffffffffu, sum0, 2);
        sum1 += __shfl_xor_sync(0xffffffffu, sum1, 1);
        sum1 += __shfl_xor_sync(0xffffffffu, sum1, 2);
        l0 = l0 * c0 + sum0;
        l1 = l1 * c1 + sum1;
#pragma unroll
        for (int nd = 0; nd < 8; nd++) {
            o[nd][0] *= c0; o[nd][1] *= c0;
            o[nd][2] *= c1; o[nd][3] *= c1;
        }

#pragma unroll
        for (int ks2 = 0; ks2 < 4; ks2++) {
            uint32_t pf[4];
            pf[0] = packbf(s[2 * ks2][0],     s[2 * ks2][1]);
            pf[1] = packbf(s[2 * ks2][2],     s[2 * ks2][3]);
            pf[2] = packbf(s[2 * ks2 + 1][0], s[2 * ks2 + 1][1]);
            pf[3] = packbf(s[2 * ks2 + 1][2], s[2 * ks2 + 1][3]);
            uint32_t vm[4][4];
#pragma unroll
            for (int p = 0; p < 4; p++)
                ldm_x4_t(vm[p], sV + (ks2 * 16 + lmrow) * GROWB + p * 32 + lmsel);
#pragma unroll
            for (int nd = 0; nd < 8; nd++) {
                uint32_t bf[2] = { vm[nd >> 1][(nd & 1) * 2], vm[nd >> 1][(nd & 1) * 2 + 1] };
                mma_bf16(o[nd], pf, bf);
            }
        }
    }

    const float inv0 = 1.0f / l0;
    const float inv1 = 1.0f / l1;
    const int tokA = q0 + wrow + g;
    const int tokB = tokA + 8;
    const size_t rA = (size_t)(b * SEQ + tokA) * ETOT + h * HD;
    const size_t rB = (size_t)(b * SEQ + tokB) * ETOT + h * HD;
#pragma unroll
    for (int nd = 0; nd < 8; nd++) {
        const int n = nd * 8 + 2 * cg;
        *(uint32_t*)(out + rA + n) = packbf(o[nd][0] * inv0, o[nd][1] * inv0);
        *(uint32_t*)(out + rB + n) = packbf(o[nd][2] * inv1, o[nd][3] * inv1);
    }
}

// ---------------------------------------------------------------------------
// Host launcher
// ---------------------------------------------------------------------------
extern "C" void kernel_launch(void* const* d_in, const int* in_sizes, int n_in,
                              void* d_out, int out_size)
{
    const float* x     = (const float*)d_in[0];
    const float* qkv_w = (const float*)d_in[1];
    const float* fc_w  = (const float*)d_in[2];
    const float* fc_b  = (const float*)d_in[3];
    const float* ln1_g = (const float*)d_in[4];
    const float* ln1_b = (const float*)d_in[5];
    const float* ln2_g = (const float*)d_in[6];
    const float* ln2_b = (const float*)d_in[7];
    const float* w1    = (const float*)d_in[8];
    const float* b1    = (const float*)d_in[9];
    const float* w2    = (const float*)d_in[10];
    const float* b2    = (const float*)d_in[11];
    float* out = (float*)d_out;

    void *ph, *pq, *pa, *px2, *pm, *pwq, *pwf, *pw1, *pw2;
    cudaGetSymbolAddress(&ph,  g_h);
    cudaGetSymbolAddress(&pq,  g_qkv);
    cudaGetSymbolAddress(&pa,  g_attn);
    cudaGetSymbolAddress(&px2, g_x2);
    cudaGetSymbolAddress(&pm,  g_mid);
    cudaGetSymbolAddress(&pwq, g_wq);
    cudaGetSymbolAddress(&pwf, g_wf);
    cudaGetSymbolAddress(&pw1, g_w1);
    cudaGetSymbolAddress(&pw2, g_w2);
    __nv_bfloat16* h    = (__nv_bfloat16*)ph;
    __nv_bfloat16* qkvb = (__nv_bfloat16*)pq;
    __nv_bfloat16* attn = (__nv_bfloat16*)pa;
    float*         x2   = (float*)px2;
    __nv_bfloat16* mid  = (__nv_bfloat16*)pm;
    __nv_bfloat16* wq   = (__nv_bfloat16*)pwq;
    __nv_bfloat16* wf   = (__nv_bfloat16*)pwf;
    __nv_bfloat16* w1r  = (__nv_bfloat16*)pw1;
    __nv_bfloat16* w2r  = (__nv_bfloat16*)pw2;

    cudaFuncSetAttribute(bf_gemm<8, false, false, false, true>,
                         cudaFuncAttributeMaxDynamicSharedMemorySize, SMEM_G8);
    cudaFuncSetAttribute(bf_gemm<4, true, true, false, false>,
                         cudaFuncAttributeMaxDynamicSharedMemorySize, SMEM_G4);
    cudaFuncSetAttribute(bf_gemm<8, true, false, true, true>,
                         cudaFuncAttributeMaxDynamicSharedMemorySize, SMEM_G8);
    cudaFuncSetAttribute(bf_gemm<8, true, true, false, false>,
                         cudaFuncAttributeMaxDynamicSharedMemorySize, SMEM_G8);
    cudaFuncSetAttribute(attn_mma,
                         cudaFuncAttributeMaxDynamicSharedMemorySize, SMEM_ATTN);

    // 0. Convert all weights to bf16 (single launch)
    round_all<<<ROUND_BLOCKS, 256>>>(qkv_w, fc_w, w1, w2, wq, wf, w1r, w2r);

    // 1. h = LN1(x) -> bf16
    ln_kernel<<<NTOK, 256>>>(x, ln1_g, ln1_b, h);

    // 2. qkv = h @ qkv_w^T -> bf16   (128x256 tiles)
    bf_gemm<8, false, false, false, true>
        <<<dim3((3 * ETOT) / 256, NTOK / 128), 256, SMEM_G8>>>(
        h, wq, nullptr, nullptr, nullptr, qkvb, NTOK, 3 * ETOT, ETOT);

    // 3. attention -> bf16
    attn_mma<<<dim3(SEQ / AQ, 4 * NH), 256, SMEM_ATTN>>>(qkvb, attn);

    // 4. x2 = x + attn @ fc_w^T + fc_b -> fp32   (128x128 tiles)
    bf_gemm<4, true, true, false, false>
        <<<dim3(ETOT / 128, NTOK / 128), 256, SMEM_G4>>>(
        attn, wf, fc_b, x, x2, nullptr, NTOK, ETOT, ETOT);

    // 5. h = LN2(x2) -> bf16
    ln_kernel<<<NTOK, 256>>>(x2, ln2_g, ln2_b, h);

    // 6. mid = gelu(h @ w1^T + b1) -> bf16   (128x256 tiles)
    bf_gemm<8, true, false, true, true>
        <<<dim3(MLPD / 256, NTOK / 128), 256, SMEM_G8>>>(
        h, w1r, b1, nullptr, nullptr, mid, NTOK, MLPD, ETOT);

    // 7. out = x2 + mid @ w2^T + b2 -> fp32   (128x256 tiles)
    bf_gemm<8, true, true, false, false>
        <<<dim3(ETOT / 256, NTOK / 128), 256, SMEM_G8>>>(
        mid, w2r, b2, x2, out, nullptr, NTOK, ETOT, MLPD);
}

// round 15
// speedup vs baseline: 1.9483x; 1.0235x over previous
#include <cuda_runtime.h>
#include <cuda_bf16.h>
#include <math.h>
#include <stdint.h>

// Problem constants
#define ETOT 1024
#define NTOK 8192
#define SEQ  2048
#define NH   16
#define HD   64
#define MLPD 4096

#define GROWB 144                              // smem row stride bytes (64 bf16 + 16B pad)
#define GSTAGES 3

// Attention config (widened: 8 warps x 32 q-rows = 256 q/CTA)
#define AQ 256
#define AKV 64
#define KV_STAGE (2 * 64 * GROWB)
#define KVSTAGES 3
#define SMEM_ATTN (AQ * GROWB + KVSTAGES * KV_STAGE)   // 92160 B

#define LOG2E 1.4426950408889634f
#define SSCALE (0.125f * LOG2E)

// Scratch (allocation-free rule: __device__ globals)
__device__ __nv_bfloat16 g_h[NTOK * ETOT];
__device__ __nv_bfloat16 g_qkv[NTOK * 3 * ETOT];
__device__ __nv_bfloat16 g_attn[NTOK * ETOT];
__device__ float         g_x2[NTOK * ETOT];
__device__ __nv_bfloat16 g_mid[NTOK * MLPD];
__device__ __nv_bfloat16 g_wq[3 * ETOT * ETOT];
__device__ __nv_bfloat16 g_wf[ETOT * ETOT];
__device__ __nv_bfloat16 g_w1[MLPD * ETOT];
__device__ __nv_bfloat16 g_w2[ETOT * MLPD];

// ---------------------------------------------------------------------------
// Helpers
// ---------------------------------------------------------------------------
__device__ __forceinline__ uint32_t packbf(float lo, float hi) {
    uint32_t r;
    asm("cvt.rn.bf16x2.f32 %0, %1, %2;" : "=r"(r) : "f"(hi), "f"(lo));
    return r;
}

__device__ __forceinline__ void mma_bf16(float* d, const uint32_t* a,
                                         const uint32_t* b) {
    asm volatile(
        "mma.sync.aligned.m16n8k16.row.col.f32.bf16.bf16.f32 "
        "{%0,%1,%2,%3}, {%4,%5,%6,%7}, {%8,%9}, {%0,%1,%2,%3};"
        : "+f"(d[0]), "+f"(d[1]), "+f"(d[2]), "+f"(d[3])
        : "r"(a[0]), "r"(a[1]), "r"(a[2]), "r"(a[3]), "r"(b[0]), "r"(b[1]));
}

__device__ __forceinline__ void ldm_x4(uint32_t* r, uint32_t addr) {
    asm volatile("ldmatrix.sync.aligned.m8n8.x4.shared.b16 {%0,%1,%2,%3}, [%4];"
                 : "=r"(r[0]), "=r"(r[1]), "=r"(r[2]), "=r"(r[3]) : "r"(addr));
}

__device__ __forceinline__ void ldm_x4_t(uint32_t* r, uint32_t addr) {
    asm volatile("ldmatrix.sync.aligned.m8n8.x4.trans.shared.b16 {%0,%1,%2,%3}, [%4];"
                 : "=r"(r[0]), "=r"(r[1]), "=r"(r[2]), "=r"(r[3]) : "r"(addr));
}

__device__ __forceinline__ void cp16(uint32_t dst_smem, const void* src) {
    asm volatile("cp.async.cg.shared.global [%0], [%1], 16;"
                 :: "r"(dst_smem), "l"(src));
}

__device__ __forceinline__ uint32_t smem_u32(const void* p) {
    uint32_t a;
    asm("{ .reg .u64 t; cvta.to.shared.u64 t, %1; cvt.u32.u64 %0, t; }"
        : "=r"(a) : "l"(p));
    return a;
}

// ---------------------------------------------------------------------------
// Fused weight conversion fp32 -> bf16 (single launch, 4 segments of float4)
// ---------------------------------------------------------------------------
__global__ __launch_bounds__(256) void round_all(
    const float* __restrict__ qkv_w, const float* __restrict__ fc_w,
    const float* __restrict__ w1, const float* __restrict__ w2,
    __nv_bfloat16* __restrict__ owq, __nv_bfloat16* __restrict__ owf,
    __nv_bfloat16* __restrict__ ow1, __nv_bfloat16* __restrict__ ow2)
{
    int i = blockIdx.x * 256 + threadIdx.x;
    const float4* src;
    __nv_bfloat16* dst;
    if (i < 786432) {
        src = (const float4*)qkv_w; dst = owq;
    } else if (i < 786432 + 262144) {
        i -= 786432;
        src = (const float4*)fc_w; dst = owf;
    } else if (i < 786432 + 262144 + 1048576) {
        i -= 786432 + 262144;
        src = (const float4*)w1; dst = ow1;
    } else {
        i -= 786432 + 262144 + 1048576;
        src = (const float4*)w2; dst = ow2;
    }
    const float4 v = src[i];
    uint2 w;
    w.x = packbf(v.x, v.y);
    w.y = packbf(v.z, v.w);
    ((uint2*)dst)[i] = w;
}
#define ROUND_BLOCKS ((786432 + 262144 + 1048576 + 1048576) / 256)

// ---------------------------------------------------------------------------
// LayerNorm: fp32 in, bf16 out
// ---------------------------------------------------------------------------
__global__ __launch_bounds__(256) void ln_kernel(
    const float* __restrict__ x, const float* __restrict__ g,
    const float* __restrict__ b, __nv_bfloat16* __restrict__ out)
{
    const int row = blockIdx.x;
    const int tid = threadIdx.x;
    const float4 v = ((const float4*)(x + (long)row * ETOT))[tid];
    float s = v.x + v.y + v.z + v.w;
    float s2 = v.x * v.x + v.y * v.y + v.z * v.z + v.w * v.w;
#pragma unroll
    for (int o = 16; o; o >>= 1) {
        s  += __shfl_down_sync(0xffffffffu, s, o);
        s2 += __shfl_down_sync(0xffffffffu, s2, o);
    }
    __shared__ float sm[8], sm2[8];
    if ((tid & 31) == 0) { sm[tid >> 5] = s; sm2[tid >> 5] = s2; }
    __syncthreads();
    float ts = 0.f, ts2 = 0.f;
#pragma unroll
    for (int i = 0; i < 8; i++) { ts += sm[i]; ts2 += sm2[i]; }
    const float mu = ts * (1.0f / ETOT);
    const float var = ts2 * (1.0f / ETOT) - mu * mu;
    const float r = rsqrtf(var + 1e-5f);
    const float4 gv = ((const float4*)g)[tid];
    const float4 bv = ((const float4*)b)[tid];
    uint2 w;
    w.x = packbf((v.x - mu) * r * gv.x + bv.x, (v.y - mu) * r * gv.y + bv.y);
    w.y = packbf((v.z - mu) * r * gv.z + bv.z, (v.w - mu) * r * gv.w + bv.w);
    ((uint2*)(out + (long)row * ETOT))[tid] = w;
}

// ---------------------------------------------------------------------------
// bf16 GEMM: C[M,N] = A[M,K] @ W[N,K]^T (+bias)(+GELU)(+residual)
// NJ=4 -> 128x128 tile (2 CTAs/SM); NJ=8 -> 128x256 tile, 64x64 warp (1 CTA/SM)
// QSC: scale output by SSCALE for columns n < 1024 (Q prescale for attention)
// ---------------------------------------------------------------------------
template <int NJ, bool BIAS, bool RES, bool GELU, bool OUTBF, bool QSC>
__global__ __launch_bounds__(256, (NJ == 4) ? 2 : 1) void bf_gemm(
    const __nv_bfloat16* __restrict__ A, const __nv_bfloat16* __restrict__ W,
    const float* __restrict__ bias, const float* __restrict__ res,
    float* __restrict__ Cf, __nv_bfloat16* __restrict__ Cb,
    int M, int N, int K)
{
    constexpr int BNRows = NJ * 32;
    constexpr int STAGE = (128 + BNRows) * GROWB;

    extern __shared__ char smem[];
    const uint32_t sb = smem_u32(smem);

    const int tid = threadIdx.x;
    const int m0 = blockIdx.y * 128;
    const int n0 = blockIdx.x * (NJ * 32);

    const int wid = tid >> 5;
    const int lane = tid & 31;
    const int wm = (wid >> 2) * 64;
    const int wn = (wid & 3) * (NJ * 8);
    const int g = lane >> 2;
    const int cg = lane & 3;
    const uint32_t lmrow = (lane & 15);
    const uint32_t lmsel = ((lane >> 4) & 1) * 16;

    float acc[4][NJ][4];
#pragma unroll
    for (int mi = 0; mi < 4; mi++)
#pragma unroll
        for (int nj = 0; nj < NJ; nj++)
#pragma unroll
            for (int e = 0; e < 4; e++) acc[mi][nj][e] = 0.f;

    auto issue = [&](int st, int kt) {
        const uint32_t dA = sb + st * STAGE;
        const uint32_t dB = dA + 128 * GROWB;
#pragma unroll
        for (int j = 0; j < 4; j++) {
            const int idx = tid + j * 256;
            const int r = idx >> 3, c = idx & 7;
            cp16(dA + r * GROWB + c * 16, A + (size_t)(m0 + r) * K + kt + c * 8);
        }
#pragma unroll
        for (int j = 0; j < NJ; j++) {
            const int idx = tid + j * 256;
            const int r = idx >> 3, c = idx & 7;
            cp16(dB + r * GROWB + c * 16, W + (size_t)(n0 + r) * K + kt + c * 8);
        }
        asm volatile("cp.async.commit_group;");
    };

    const int T = K / 64;
    issue(0, 0);
    issue(1, 64);

    for (int t = 0; t < T; t++) {
        if (t + 1 < T) asm volatile("cp.async.wait_group 1;");
        else           asm volatile("cp.async.wait_group 0;");
        __syncthreads();

        if (t + 2 < T) issue((t + 2) % GSTAGES, (t + 2) * 64);

        const uint32_t sA = sb + (t % GSTAGES) * STAGE;
        const uint32_t sB = sA + 128 * GROWB;

#pragma unroll
        for (int ks = 0; ks < 4; ks++) {
            uint32_t af[4][4];
#pragma unroll
            for (int mi = 0; mi < 4; mi++)
                ldm_x4(af[mi], sA + (wm + mi * 16 + lmrow) * GROWB + ks * 32 + lmsel);
            uint32_t bm[NJ / 2][4];
#pragma unroll
            for (int p = 0; p < NJ / 2; p++)
                ldm_x4(bm[p], sB + (wn + p * 16 + lmrow) * GROWB + ks * 32 + lmsel);
#pragma unroll
            for (int mi = 0; mi < 4; mi++)
#pragma unroll
                for (int nj = 0; nj < NJ; nj++) {
                    uint32_t bf[2] = { bm[nj >> 1][nj & 1], bm[nj >> 1][(nj & 1) + 2] };
                    mma_bf16(acc[mi][nj], af[mi], bf);
                }
        }
    }

    // Epilogue
#pragma unroll
    for (int mi = 0; mi < 4; mi++) {
        const int mA = m0 + wm + mi * 16 + g;
        const int mB = mA + 8;
#pragma unroll
        for (int nj = 0; nj < NJ; nj++) {
            const int n = n0 + wn + nj * 8 + 2 * cg;
            float2 v0 = make_float2(acc[mi][nj][0], acc[mi][nj][1]);
            float2 v1 = make_float2(acc[mi][nj][2], acc[mi][nj][3]);
            if (BIAS) {
                const float b0 = bias[n], b1 = bias[n + 1];
                v0.x += b0; v0.y += b1;
                v1.x += b0; v1.y += b1;
            }
            if (GELU) {
                v0.x = 0.5f * v0.x * (1.0f + erff(v0.x * 0.70710678118654752f));
                v0.y = 0.5f * v0.y * (1.0f + erff(v0.y * 0.70710678118654752f));
                v1.x = 0.5f * v1.x * (1.0f + erff(v1.x * 0.70710678118654752f));
                v1.y = 0.5f * v1.y * (1.0f + erff(v1.y * 0.70710678118654752f));
            }
            if (RES) {
                const float2 r0 = *(const float2*)(res + (size_t)mA * N + n);
                const float2 r1 = *(const float2*)(res + (size_t)mB * N + n);
                v0.x += r0.x; v0.y += r0.y;
                v1.x += r1.x; v1.y += r1.y;
            }
            if (QSC) {
                if (n < ETOT) {   // Q columns: fold softmax scale (fp32, pre-round)
                    v0.x *= SSCALE; v0.y *= SSCALE;
                    v1.x *= SSCALE; v1.y *= SSCALE;
                }
            }
            if (OUTBF) {
                *(uint32_t*)(Cb + (size_t)mA * N + n) = packbf(v0.x, v0.y);
                *(uint32_t*)(Cb + (size_t)mB * N + n) = packbf(v1.x, v1.y);
            } else {
                *(float2*)(Cf + (size_t)mA * N + n) = v0;
                *(float2*)(Cf + (size_t)mB * N + n) = v1;
            }
        }
    }
}

#define SMEM_G4 (GSTAGES * (128 + 128) * GROWB)   // 110592
#define SMEM_G8 (GSTAGES * (128 + 256) * GROWB)   // 165888

// ---------------------------------------------------------------------------
// bf16 flash attention, widened: 8 warps x 32 q-rows (AQ=256), max-free
// softmax in exp2 domain (scores pre-scaled by 0.125*log2e in QKV GEMM).
// grid = (SEQ/256, B*NH).
// ---------------------------------------------------------------------------
__global__ __launch_bounds__(256, 1) void attn_mma(
    const __nv_bfloat16* __restrict__ qkv, __nv_bfloat16* __restrict__ out)
{
    extern __shared__ char smem[];
    const uint32_t sq = smem_u32(smem);
    const uint32_t skv = sq + AQ * GROWB;

    const int bh = blockIdx.y;
    const int b = bh >> 4;
    const int h = bh & 15;
    const int q0 = blockIdx.x * AQ;
    const int tid = threadIdx.x;
    const int wid = tid >> 5;
    const int lane = tid & 31;
    const int g = lane >> 2;
    const int cg = lane & 3;
    const int wrow = wid * 32;
    const uint32_t lmrow = (lane & 15);
    const uint32_t lmsel = ((lane >> 4) & 1) * 16;

    const size_t base = (size_t)b * SEQ * 3 * ETOT;

    // Stage Q (256 rows x 128B)
#pragma unroll
    for (int it = 0; it < 8; it++) {
        const int idx = tid + it * 256;
        const int r = idx >> 3, c = idx & 7;
        const uint4 v = *(const uint4*)(qkv + base + (size_t)(q0 + r) * (3 * ETOT) + h * HD + c * 8);
        *(uint4*)(smem + r * GROWB + c * 16) = v;
    }

    // KV loader
    const int r2 = tid >> 2;
    const int c2 = tid & 3;
    const __nv_bfloat16* gkb = qkv + base + ETOT + h * HD + c2 * 8 + (size_t)r2 * (3 * ETOT);
    auto issueKV = [&](int st, int k0) {
        const uint32_t dK = skv + st * KV_STAGE + r2 * GROWB + c2 * 16;
        const uint32_t dV = dK + 64 * GROWB;
        const __nv_bfloat16* gk = gkb + (size_t)k0 * (3 * ETOT);
        cp16(dK, gk);
        cp16(dK + 64, gk + 32);
        cp16(dV, gk + ETOT);
        cp16(dV + 64, gk + ETOT + 32);
        asm volatile("cp.async.commit_group;");
    };

    issueKV(0, 0);
    issueKV(1, AKV);
    __syncthreads();

    // Persistent Q fragments (2 row-groups x 4 k-steps)
    uint32_t qf[2][4][4];
#pragma unroll
    for (int mi = 0; mi < 2; mi++)
#pragma unroll
        for (int ks = 0; ks < 4; ks++)
            ldm_x4(qf[mi][ks], sq + (wrow + mi * 16 + lmrow) * GROWB + ks * 32 + lmsel);

    float o[2][8][4];
#pragma unroll
    for (int mi = 0; mi < 2; mi++)
#pragma unroll
        for (int nd = 0; nd < 8; nd++)
#pragma unroll
            for (int e = 0; e < 4; e++) o[mi][nd][e] = 0.f;
    float lsum[4] = {0.f, 0.f, 0.f, 0.f};

    const int NC = SEQ / AKV;
    for (int c = 0; c < NC; c++) {
        if (c + 1 < NC) asm volatile("cp.async.wait_group 1;");
        else            asm volatile("cp.async.wait_group 0;");
        __syncthreads();

        if (c + 2 < NC) issueKV((c + 2) % KVSTAGES, (c + 2) * AKV);

        const uint32_t sK = skv + (c % KVSTAGES) * KV_STAGE;
        const uint32_t sV = sK + 64 * GROWB;

        // S = (Q*scale) @ K^T   (exp2-domain scores)
        float s[2][8][4];
#pragma unroll
        for (int mi = 0; mi < 2; mi++)
#pragma unroll
            for (int nj = 0; nj < 8; nj++)
#pragma unroll
                for (int e = 0; e < 4; e++) s[mi][nj][e] = 0.f;
#pragma unroll
        for (int ks = 0; ks < 4; ks++) {
            uint32_t km[4][4];
#pragma unroll
            for (int p = 0; p < 4; p++)
                ldm_x4(km[p], sK + (p * 16 + lmrow) * GROWB + ks * 32 + lmsel);
#pragma unroll
            for (int mi = 0; mi < 2; mi++)
#pragma unroll
                for (int nj = 0; nj < 8; nj++) {
                    uint32_t bf[2] = { km[nj >> 1][nj & 1], km[nj >> 1][(nj & 1) + 2] };
                    mma_bf16(s[mi][nj], qf[mi][ks], bf);
                }
        }

        // Max-free softmax: P = exp2(S); accumulate per-thread row sums
#pragma unroll
        for (int mi = 0; mi < 2; mi++) {
            float a0 = 0.f, a1 = 0.f;
#pragma unroll
            for (int nj = 0; nj < 8; nj++) {
                s[mi][nj][0] = exp2f(s[mi][nj][0]);
                s[mi][nj][1] = exp2f(s[mi][nj][1]);
                s[mi][nj][2] = exp2f(s[mi][nj][2]);
                s[mi][nj][3] = exp2f(s[mi][nj][3]);
                a0 += s[mi][nj][0] + s[mi][nj][1];
                a1 += s[mi][nj][2] + s[mi][nj][3];
            }
            lsum[2 * mi + 0] += a0;
            lsum[2 * mi + 1] += a1;
        }

        // O += P @ V
#pragma unroll
        for (int ks2 = 0; ks2 < 4; ks2++) {
            uint32_t vm[4][4];
#pragma unroll
            for (int p = 0; p < 4; p++)
                ldm_x4_t(vm[p], sV + (ks2 * 16 + lmrow) * GROWB + p * 32 + lmsel);
#pragma unroll
            for (int mi = 0; mi < 2; mi++) {
                uint32_t pf[4];
                pf[0] = packbf(s[mi][2 * ks2][0],     s[mi][2 * ks2][1]);
                pf[1] = packbf(s[mi][2 * ks2][2],     s[mi][2 * ks2][3]);
                pf[2] = packbf(s[mi][2 * ks2 + 1][0], s[mi][2 * ks2 + 1][1]);
                pf[3] = packbf(s[mi][2 * ks2 + 1][2], s[mi][2 * ks2 + 1][3]);
#pragma unroll
                for (int nd = 0; nd < 8; nd++) {
                    uint32_t bf[2] = { vm[nd >> 1][(nd & 1) * 2], vm[nd >> 1][(nd & 1) * 2 + 1] };
                    mma_bf16(o[mi][nd], pf, bf);
                }
            }
        }
    }

    // Reduce row sums over quad (once), normalize, write bf16
#pragma unroll
    for (int i = 0; i < 4; i++) {
        lsum[i] += __shfl_xor_sync(0xffffffffu, lsum[i], 1);
        lsum[i] += __shfl_xor_sync(0xffffffffu, lsum[i], 2);
        lsum[i] = 1.0f / lsum[i];
    }
#pragma unroll
    for (int mi = 0; mi < 2; mi++) {
        const int tokA = q0 + wrow + mi * 16 + g;
        const int tokB = tokA + 8;
        const size_t rA = (size_t)(b * SEQ + tokA) * ETOT + h * HD;
        const size_t rB = (size_t)(b * SEQ + tokB) * ETOT + h * HD;
        const float inv0 = lsum[2 * mi + 0];
        const float inv1 = lsum[2 * mi + 1];
#pragma unroll
        for (int nd = 0; nd < 8; nd++) {
            const int n = nd * 8 + 2 * cg;
            *(uint32_t*)(out + rA + n) = packbf(o[mi][nd][0] * inv0, o[mi][nd][1] * inv0);
            *(uint32_t*)(out + rB + n) = packbf(o[mi][nd][2] * inv1, o[mi][nd][3] * inv1);
        }
    }
}

// ---------------------------------------------------------------------------
// Host launcher
// ---------------------------------------------------------------------------
extern "C" void kernel_launch(void* const* d_in, const int* in_sizes, int n_in,
                              void* d_out, int out_size)
{
    const float* x     = (const float*)d_in[0];
    const float* qkv_w = (const float*)d_in[1];
    const float* fc_w  = (const float*)d_in[2];
    const float* fc_b  = (const float*)d_in[3];
    const float* ln1_g = (const float*)d_in[4];
    const float* ln1_b = (const float*)d_in[5];
    const float* ln2_g = (const float*)d_in[6];
    const float* ln2_b = (const float*)d_in[7];
    const float* w1    = (const float*)d_in[8];
    const float* b1    = (const float*)d_in[9];
    const float* w2    = (const float*)d_in[10];
    const float* b2    = (const float*)d_in[11];
    float* out = (float*)d_out;

    void *ph, *pq, *pa, *px2, *pm, *pwq, *pwf, *pw1, *pw2;
    cudaGetSymbolAddress(&ph,  g_h);
    cudaGetSymbolAddress(&pq,  g_qkv);
    cudaGetSymbolAddress(&pa,  g_attn);
    cudaGetSymbolAddress(&px2, g_x2);
    cudaGetSymbolAddress(&pm,  g_mid);
    cudaGetSymbolAddress(&pwq, g_wq);
    cudaGetSymbolAddress(&pwf, g_wf);
    cudaGetSymbolAddress(&pw1, g_w1);
    cudaGetSymbolAddress(&pw2, g_w2);
    __nv_bfloat16* h    = (__nv_bfloat16*)ph;
    __nv_bfloat16* qkvb = (__nv_bfloat16*)pq;
    __nv_bfloat16* attn = (__nv_bfloat16*)pa;
    float*         x2   = (float*)px2;
    __nv_bfloat16* mid  = (__nv_bfloat16*)pm;
    __nv_bfloat16* wq   = (__nv_bfloat16*)pwq;
    __nv_bfloat16* wf   = (__nv_bfloat16*)pwf;
    __nv_bfloat16* w1r  = (__nv_bfloat16*)pw1;
    __nv_bfloat16* w2r  = (__nv_bfloat16*)pw2;

    cudaFuncSetAttribute(bf_gemm<8, false, false, false, true, true>,
                         cudaFuncAttributeMaxDynamicSharedMemorySize, SMEM_G8);
    cudaFuncSetAttribute(bf_gemm<4, true, true, false, false, false>,
                         cudaFuncAttributeMaxDynamicSharedMemorySize, SMEM_G4);
    cudaFuncSetAttribute(bf_gemm<8, true, false, true, true, false>,
                         cudaFuncAttributeMaxDynamicSharedMemorySize, SMEM_G8);
    cudaFuncSetAttribute(bf_gemm<8, true, true, false, false, false>,
                         cudaFuncAttributeMaxDynamicSharedMemorySize, SMEM_G8);
    cudaFuncSetAttribute(attn_mma,
                         cudaFuncAttributeMaxDynamicSharedMemorySize, SMEM_ATTN);

    // 0. Convert all weights to bf16 (single launch)
    round_all<<<ROUND_BLOCKS, 256>>>(qkv_w, fc_w, w1, w2, wq, wf, w1r, w2r);

    // 1. h = LN1(x) -> bf16
    ln_kernel<<<NTOK, 256>>>(x, ln1_g, ln1_b, h);

    // 2. qkv = h @ qkv_w^T -> bf16 (Q columns pre-scaled by 0.125*log2e)
    bf_gemm<8, false, false, false, true, true>
        <<<dim3((3 * ETOT) / 256, NTOK / 128), 256, SMEM_G8>>>(
        h, wq, nullptr, nullptr, nullptr, qkvb, NTOK, 3 * ETOT, ETOT);

    // 3. attention -> bf16
    attn_mma<<<dim3(SEQ / AQ, 4 * NH), 256, SMEM_ATTN>>>(qkvb, attn);

    // 4. x2 = x + attn @ fc_w^T + fc_b -> fp32   (128x128 tiles)
    bf_gemm<4, true, true, false, false, false>
        <<<dim3(ETOT / 128, NTOK / 128), 256, SMEM_G4>>>(
        attn, wf, fc_b, x, x2, nullptr, NTOK, ETOT, ETOT);

    // 5. h = LN2(x2) -> bf16
    ln_kernel<<<NTOK, 256>>>(x2, ln2_g, ln2_b, h);

    // 6. mid = gelu(h @ w1^T + b1) -> bf16   (128x256 tiles)
    bf_gemm<8, true, false, true, true, false>
        <<<dim3(MLPD / 256, NTOK / 128), 256, SMEM_G8>>>(
        h, w1r, b1, nullptr, nullptr, mid, NTOK, MLPD, ETOT);

    // 7. out = x2 + mid @ w2^T + b2 -> fp32   (128x256 tiles)
    bf_gemm<8, true, true, false, false, false>
        <<<dim3(ETOT / 256, NTOK / 128), 256, SMEM_G8>>>(
        mid, w2r, b2, x2, out, nullptr, NTOK, ETOT, MLPD);
}